// round 6
// baseline (speedup 1.0000x reference)
#include <cuda_runtime.h>
#include <cstdint>
#include <math.h>

#define B_   2
#define T_   2048
#define D_   2048
#define NH   16
#define NKV  8
#define HD   128
#define KVD  1024
#define BT   4096

// ---------------- scratch (device globals; allocation-free) ----------------
__device__ float g_xr [(size_t)BT  * D_ ];
__device__ float g_Wqr[(size_t)D_  * D_ ];
__device__ float g_Wkr[(size_t)KVD * D_ ];
__device__ float g_Wvr[(size_t)KVD * D_ ];
__device__ float g_Wor[(size_t)D_  * D_ ];
__device__ float g_Q  [(size_t)BT  * D_ ];
__device__ float g_K  [(size_t)BT  * KVD];
__device__ float g_V  [(size_t)BT  * KVD];
__device__ float g_O  [(size_t)BT  * D_ ];

// ---------------- helpers ----------------
__device__ __forceinline__ uint32_t smem_u32(const void* p) {
    uint32_t a;
    asm("{ .reg .u64 t; cvta.to.shared.u64 t, %1; cvt.u32.u64 %0, t; }" : "=r"(a) : "l"(p));
    return a;
}
__device__ __forceinline__ float rtf32(float x) {
    uint32_t r; asm("cvt.rna.tf32.f32 %0, %1;" : "=r"(r) : "f"(x));
    return __uint_as_float(r);
}
__device__ __forceinline__ void cpa16(uint32_t dst, const float* src) {
    asm volatile("cp.async.cg.shared.global [%0], [%1], 16;" :: "r"(dst), "l"(src) : "memory");
}
__device__ __forceinline__ void mma_tf32(float* c, const uint32_t* a, const uint32_t* b) {
    asm volatile("mma.sync.aligned.m16n8k8.row.col.f32.tf32.tf32.f32 "
        "{%0,%1,%2,%3}, {%4,%5,%6,%7}, {%8,%9}, {%0,%1,%2,%3};"
        : "+f"(c[0]), "+f"(c[1]), "+f"(c[2]), "+f"(c[3])
        : "r"(a[0]), "r"(a[1]), "r"(a[2]), "r"(a[3]), "r"(b[0]), "r"(b[1]));
}

// ---------------------------------------------------------------------------
// tf32 MMA GEMM tile: C[128 x 256] = alpha * A @ B^T (A, B K-contiguous)
// 8 warps (2x4), warp tile 64x64. 3-stage cp.async, one barrier per chunk.
// smem: As[3][128][20] + Bs[3][256][20] = 92160 B.
// ---------------------------------------------------------------------------
#define GROW 20
#define ABUF (128 * GROW)
#define BBUF (256 * GROW)
#define GEMM_SMEM (3 * (ABUF + BBUF) * 4)   // 92160 bytes

__device__ __forceinline__ void gemm_mma_body(
    const float* __restrict__ A, int lda,
    const float* __restrict__ B, int ldb,
    float* __restrict__ C, int ldc,
    int K, float alpha, bool round_out, int m0, int n0)
{
    extern __shared__ float gsm[];
    float* As = gsm;                 // 3 * 2560 floats
    float* Bs = gsm + 3 * ABUF;      // 3 * 5120 floats

    const int tid  = threadIdx.x;
    const int lane = tid & 31;
    const int w    = tid >> 5;
    const int g    = lane >> 2;
    const int tg   = lane & 3;
    const int wm   = (w >> 2) << 6;    // 0 / 64
    const int wn   = (w & 3)  << 6;    // 0/64/128/192

    float acc[4][8][4];
    #pragma unroll
    for (int i = 0; i < 4; ++i)
        #pragma unroll
        for (int j = 0; j < 8; ++j)
            #pragma unroll
            for (int r = 0; r < 4; ++r)
                acc[i][j][r] = 0.0f;

    const float* Ab = A + (size_t)m0 * lda;
    const float* Bb = B + (size_t)n0 * ldb;
    const int nk = K >> 4;

    // per-thread load coords: A 512 f4 (2/thr), B 1024 f4 (4/thr)
    const int ar0 = tid >> 2,  ac = (tid & 3) << 2;
    const int ar1 = ar0 + 64;

    auto load_chunk = [&](int chunk) {
        const int st = chunk % 3;
        const int kt = chunk << 4;
        uint32_t aDst = smem_u32(As + st * ABUF);
        uint32_t bDst = smem_u32(Bs + st * BBUF);
        cpa16(aDst + (ar0 * GROW + ac) * 4, Ab + (size_t)ar0 * lda + kt + ac);
        cpa16(aDst + (ar1 * GROW + ac) * 4, Ab + (size_t)ar1 * lda + kt + ac);
        #pragma unroll
        for (int j = 0; j < 4; ++j) {
            int r = ar0 + (j << 6);
            cpa16(bDst + (r * GROW + ac) * 4, Bb + (size_t)r * ldb + kt + ac);
        }
        asm volatile("cp.async.commit_group;" ::: "memory");
    };

    load_chunk(0);
    if (nk > 1) load_chunk(1);

    for (int i = 0; i < nk; ++i) {
        const int st = i % 3;
        if (i + 1 < nk) asm volatile("cp.async.wait_group 1;" ::: "memory");
        else            asm volatile("cp.async.wait_group 0;" ::: "memory");
        __syncthreads();
        if (i + 2 < nk) load_chunk(i + 2);  // writes stage (i-1)%3: consumed, safe

        const float* Ac = As + st * ABUF;
        const float* Bc = Bs + st * BBUF;
        #pragma unroll
        for (int ks = 0; ks < 2; ++ks) {
            const int k0 = ks << 3;
            uint32_t bf[8][2];
            #pragma unroll
            for (int nt = 0; nt < 8; ++nt) {
                const float* br = Bc + (wn + (nt << 3) + g) * GROW + k0;
                bf[nt][0] = __float_as_uint(br[tg]);
                bf[nt][1] = __float_as_uint(br[tg + 4]);
            }
            #pragma unroll
            for (int mt = 0; mt < 4; ++mt) {
                const float* ar = Ac + (wm + (mt << 4) + g) * GROW + k0;
                uint32_t af[4];
                af[0] = __float_as_uint(ar[tg]);
                af[1] = __float_as_uint(ar[8 * GROW + tg]);
                af[2] = __float_as_uint(ar[tg + 4]);
                af[3] = __float_as_uint(ar[8 * GROW + tg + 4]);
                #pragma unroll
                for (int nt = 0; nt < 8; ++nt)
                    mma_tf32(acc[mt][nt], af, bf[nt]);
            }
        }
    }

    #pragma unroll
    for (int mt = 0; mt < 4; ++mt) {
        const int rr = m0 + wm + (mt << 4) + g;
        #pragma unroll
        for (int nt = 0; nt < 8; ++nt) {
            const int cb = n0 + wn + (nt << 3) + (tg << 1);
            float2 v0, v1;
            v0.x = acc[mt][nt][0] * alpha;  v0.y = acc[mt][nt][1] * alpha;
            v1.x = acc[mt][nt][2] * alpha;  v1.y = acc[mt][nt][3] * alpha;
            if (round_out) {
                v0.x = rtf32(v0.x); v0.y = rtf32(v0.y);
                v1.x = rtf32(v1.x); v1.y = rtf32(v1.y);
            }
            *(float2*)(C + (size_t)rr * ldc + cb)       = v0;
            *(float2*)(C + (size_t)(rr + 8) * ldc + cb) = v1;
        }
    }
}

// fused QKV projection: grid.x 0..7 -> Q, 8..11 -> K, 12..15 -> V
__global__ void __launch_bounds__(256, 1)
qkv_proj(const float* __restrict__ xr,
         const float* __restrict__ Wq, const float* __restrict__ Wk,
         const float* __restrict__ Wv,
         float* __restrict__ Q, float* __restrict__ K, float* __restrict__ V)
{
    const int bx = blockIdx.x;
    const float* Bp;  float* Cp;  int ldc, n0;
    if (bx < 8)       { Bp = Wq; Cp = Q; ldc = D_;  n0 = bx * 256; }
    else if (bx < 12) { Bp = Wk; Cp = K; ldc = KVD; n0 = (bx - 8) * 256; }
    else              { Bp = Wv; Cp = V; ldc = KVD; n0 = (bx - 12) * 256; }
    gemm_mma_body(xr, D_, Bp, D_, Cp, ldc, D_, 1.0f, true,
                  blockIdx.y * 128, n0);
}

__global__ void __launch_bounds__(256, 1)
gemm_tc(const float* __restrict__ A, int lda, const float* __restrict__ B, int ldb,
        float* __restrict__ C, int ldc, int K, float alpha, int round_out)
{
    gemm_mma_body(A, lda, B, ldb, C, ldc, K, alpha, round_out != 0,
                  blockIdx.y * 128, blockIdx.x * 256);
}

// ---------------------------------------------------------------------------
// Flash attention (R4 structure; 1/sqrt(d) folded into Q fragments)
// ---------------------------------------------------------------------------
#define SK_STRIDE 132
#define SV_STRIDE 136
#define SP_STRIDE 68
#define SK_BUF (64 * SK_STRIDE)
#define SV_BUF (64 * SV_STRIDE)
#define FLASH_SMEM ((2*SK_BUF + 2*SV_BUF + 8*16*SP_STRIDE) * 4)

__global__ void __launch_bounds__(256, 1)
flash_attn(const float* __restrict__ Qg, const float* __restrict__ Kg,
           const float* __restrict__ Vg, float* __restrict__ Og)
{
    extern __shared__ float fsm[];
    float* sK = fsm;
    float* sV = fsm + 2 * SK_BUF;
    float* sP = fsm + 2 * SK_BUF + 2 * SV_BUF;

    const int tid  = threadIdx.x;
    const int lane = tid & 31;
    const int w    = tid >> 5;
    const int g    = lane >> 2;
    const int tg   = lane & 3;
    const int z    = blockIdx.y, b = z >> 4, hq = z & 15, kv = hq >> 1;
    const int m0   = blockIdx.x << 7;
    const float inv_scale = 0.088388347648318447f;

    const size_t qbase = (size_t)b * T_ * D_  + (size_t)hq * HD;
    const size_t kbase = (size_t)b * T_ * KVD + (size_t)kv * HD;

    #pragma unroll
    for (int j = 0; j < 16; ++j) {
        int u = tid + (j << 8);
        int row = u >> 5, seg = (u & 31) << 2;
        cpa16(smem_u32(sK + row * SK_STRIDE + seg),
              Qg + qbase + (size_t)(m0 + row) * D_ + seg);
    }
    asm volatile("cp.async.commit_group;" ::: "memory");
    asm volatile("cp.async.wait_group 0;" ::: "memory");
    __syncthreads();

    uint32_t qf[16][4];
    {
        const float* qr0 = sK + (w * 16 + g) * SK_STRIDE;
        const float* qr1 = qr0 + 8 * SK_STRIDE;
        #pragma unroll
        for (int ks = 0; ks < 16; ++ks) {
            qf[ks][0] = __float_as_uint(rtf32(qr0[ks * 8 + tg]     * inv_scale));
            qf[ks][1] = __float_as_uint(rtf32(qr1[ks * 8 + tg]     * inv_scale));
            qf[ks][2] = __float_as_uint(rtf32(qr0[ks * 8 + tg + 4] * inv_scale));
            qf[ks][3] = __float_as_uint(rtf32(qr1[ks * 8 + tg + 4] * inv_scale));
        }
    }
    __syncthreads();

    float of[16][4];
    #pragma unroll
    for (int nt = 0; nt < 16; ++nt)
        #pragma unroll
        for (int r = 0; r < 4; ++r)
            of[nt][r] = 0.0f;
    float mprev0 = -1e30f, mprev1 = -1e30f, l0 = 0.0f, l1 = 0.0f;

    #pragma unroll
    for (int j = 0; j < 8; ++j) {
        int u = tid + (j << 8);
        int row = u >> 5, seg = (u & 31) << 2;
        cpa16(smem_u32(sK + row * SK_STRIDE + seg), Kg + kbase + (size_t)row * KVD + seg);
        cpa16(smem_u32(sV + row * SV_STRIDE + seg), Vg + kbase + (size_t)row * KVD + seg);
    }
    asm volatile("cp.async.commit_group;" ::: "memory");

    float* Pw = sP + w * 16 * SP_STRIDE;

    for (int it = 0; it < 32; ++it) {
        const int buf = it & 1;
        if (it + 1 < 32) {
            const int nb = buf ^ 1;
            const int t0 = (it + 1) << 6;
            #pragma unroll
            for (int j = 0; j < 8; ++j) {
                int u = tid + (j << 8);
                int row = u >> 5, seg = (u & 31) << 2;
                cpa16(smem_u32(sK + nb * SK_BUF + row * SK_STRIDE + seg),
                      Kg + kbase + (size_t)(t0 + row) * KVD + seg);
                cpa16(smem_u32(sV + nb * SV_BUF + row * SV_STRIDE + seg),
                      Vg + kbase + (size_t)(t0 + row) * KVD + seg);
            }
            asm volatile("cp.async.commit_group;" ::: "memory");
            asm volatile("cp.async.wait_group 1;" ::: "memory");
        } else {
            asm volatile("cp.async.wait_group 0;" ::: "memory");
        }
        __syncthreads();

        const float* Kb = sK + buf * SK_BUF;
        const float* Vb = sV + buf * SV_BUF;

        float sf[8][4];
        #pragma unroll
        for (int nt = 0; nt < 8; ++nt)
            sf[nt][0] = sf[nt][1] = sf[nt][2] = sf[nt][3] = 0.0f;
        #pragma unroll
        for (int ks = 0; ks < 16; ++ks) {
            const int k0 = ks << 3;
            #pragma unroll
            for (int nt = 0; nt < 8; ++nt) {
                uint32_t bb[2];
                const float* kr = Kb + (nt * 8 + g) * SK_STRIDE + k0;
                bb[0] = __float_as_uint(kr[tg]);
                bb[1] = __float_as_uint(kr[tg + 4]);
                mma_tf32(sf[nt], qf[ks], bb);
            }
        }

        float mx0 = mprev0, mx1 = mprev1;
        #pragma unroll
        for (int nt = 0; nt < 8; ++nt) {
            mx0 = fmaxf(mx0, fmaxf(sf[nt][0], sf[nt][1]));
            mx1 = fmaxf(mx1, fmaxf(sf[nt][2], sf[nt][3]));
        }
        mx0 = fmaxf(mx0, __shfl_xor_sync(0xffffffffu, mx0, 1));
        mx0 = fmaxf(mx0, __shfl_xor_sync(0xffffffffu, mx0, 2));
        mx1 = fmaxf(mx1, __shfl_xor_sync(0xffffffffu, mx1, 1));
        mx1 = fmaxf(mx1, __shfl_xor_sync(0xffffffffu, mx1, 2));

        const float sc0 = __expf(mprev0 - mx0);
        const float sc1 = __expf(mprev1 - mx1);
        mprev0 = mx0; mprev1 = mx1;

        float rs0 = 0.0f, rs1 = 0.0f;
        #pragma unroll
        for (int nt = 0; nt < 8; ++nt) {
            float p0 = __expf(sf[nt][0] - mx0);
            float p1 = __expf(sf[nt][1] - mx0);
            float p2 = __expf(sf[nt][2] - mx1);
            float p3 = __expf(sf[nt][3] - mx1);
            rs0 += p0 + p1;  rs1 += p2 + p3;
            float2 st0 = make_float2(rtf32(p0), rtf32(p1));
            float2 st1 = make_float2(rtf32(p2), rtf32(p3));
            *(float2*)(Pw + g * SP_STRIDE + nt * 8 + 2 * tg)       = st0;
            *(float2*)(Pw + (g + 8) * SP_STRIDE + nt * 8 + 2 * tg) = st1;
        }
        rs0 += __shfl_xor_sync(0xffffffffu, rs0, 1);
        rs0 += __shfl_xor_sync(0xffffffffu, rs0, 2);
        rs1 += __shfl_xor_sync(0xffffffffu, rs1, 1);
        rs1 += __shfl_xor_sync(0xffffffffu, rs1, 2);
        l0 = l0 * sc0 + rs0;
        l1 = l1 * sc1 + rs1;

        #pragma unroll
        for (int nt = 0; nt < 16; ++nt) {
            of[nt][0] *= sc0; of[nt][1] *= sc0;
            of[nt][2] *= sc1; of[nt][3] *= sc1;
        }
        __syncwarp();

        #pragma unroll
        for (int kc = 0; kc < 8; ++kc) {
            uint32_t aa[4];
            const float* pr0 = Pw + g * SP_STRIDE + kc * 8;
            const float* pr1 = Pw + (g + 8) * SP_STRIDE + kc * 8;
            aa[0] = __float_as_uint(pr0[tg]);
            aa[1] = __float_as_uint(pr1[tg]);
            aa[2] = __float_as_uint(pr0[tg + 4]);
            aa[3] = __float_as_uint(pr1[tg + 4]);
            const float* vr0 = Vb + (kc * 8 + tg) * SV_STRIDE + g;
            const float* vr1 = Vb + (kc * 8 + tg + 4) * SV_STRIDE + g;
            #pragma unroll
            for (int nt = 0; nt < 16; ++nt) {
                uint32_t bb[2];
                bb[0] = __float_as_uint(vr0[nt * 8]);
                bb[1] = __float_as_uint(vr1[nt * 8]);
                mma_tf32(of[nt], aa, bb);
            }
        }
        __syncthreads();
    }

    const float i0 = 1.0f / l0;
    const float i1 = 1.0f / l1;
    const int r0 = m0 + w * 16 + g;
    const size_t obase = (size_t)b * T_ * D_ + (size_t)hq * HD;
    #pragma unroll
    for (int nt = 0; nt < 16; ++nt) {
        const int c = nt * 8 + 2 * tg;
        float2 v0 = make_float2(rtf32(of[nt][0] * i0), rtf32(of[nt][1] * i0));
        float2 v1 = make_float2(rtf32(of[nt][2] * i1), rtf32(of[nt][3] * i1));
        *(float2*)(Og + obase + (size_t)r0 * D_ + c)       = v0;
        *(float2*)(Og + obase + (size_t)(r0 + 8) * D_ + c) = v1;
    }
}

__global__ void __launch_bounds__(256)
round_inputs(const float4* __restrict__ in, float4* __restrict__ out, int n4)
{
    int i = blockIdx.x * blockDim.x + threadIdx.x;
    int stride = gridDim.x * blockDim.x;
    for (; i < n4; i += stride) {
        float4 v = in[i];
        v.x = rtf32(v.x); v.y = rtf32(v.y); v.z = rtf32(v.z); v.w = rtf32(v.w);
        out[i] = v;
    }
}

// ---------------- host ----------------
extern "C" void kernel_launch(void* const* d_in, const int* in_sizes, int n_in,
                              void* d_out, int out_size)
{
    (void)in_sizes; (void)n_in; (void)out_size;
    const float* x  = (const float*)d_in[0];
    const float* Wq = (const float*)d_in[1];
    const float* Wk = (const float*)d_in[2];
    const float* Wv = (const float*)d_in[3];
    const float* Wo = (const float*)d_in[4];
    float* out = (float*)d_out;

    float *xr, *Wqr, *Wkr, *Wvr, *Wor, *Q, *K, *V, *O;
    cudaGetSymbolAddress((void**)&xr,  g_xr);
    cudaGetSymbolAddress((void**)&Wqr, g_Wqr);
    cudaGetSymbolAddress((void**)&Wkr, g_Wkr);
    cudaGetSymbolAddress((void**)&Wvr, g_Wvr);
    cudaGetSymbolAddress((void**)&Wor, g_Wor);
    cudaGetSymbolAddress((void**)&Q,   g_Q);
    cudaGetSymbolAddress((void**)&K,   g_K);
    cudaGetSymbolAddress((void**)&V,   g_V);
    cudaGetSymbolAddress((void**)&O,   g_O);

    cudaFuncSetAttribute(qkv_proj, cudaFuncAttributeMaxDynamicSharedMemorySize,
                         GEMM_SMEM);
    cudaFuncSetAttribute(gemm_tc, cudaFuncAttributeMaxDynamicSharedMemorySize,
                         GEMM_SMEM);
    cudaFuncSetAttribute(flash_attn, cudaFuncAttributeMaxDynamicSharedMemorySize,
                         FLASH_SMEM);

    // round all MMA inputs to tf32 (unbiased rna)
    round_inputs<<<1024, 256>>>((const float4*)x,  (float4*)xr,  BT  * D_  / 4);
    round_inputs<<<1024, 256>>>((const float4*)Wq, (float4*)Wqr, D_  * D_  / 4);
    round_inputs<<<1024, 256>>>((const float4*)Wk, (float4*)Wkr, KVD * D_  / 4);
    round_inputs<<<1024, 256>>>((const float4*)Wv, (float4*)Wvr, KVD * D_  / 4);
    round_inputs<<<1024, 256>>>((const float4*)Wo, (float4*)Wor, D_  * D_  / 4);

    // fused Q/K/V projections (outputs rounded: feed attention MMAs)
    qkv_proj<<<dim3(16, 32), 256, GEMM_SMEM>>>(xr, Wqr, Wkr, Wvr, Q, K, V);

    // fused attention (scores + softmax + PV)
    flash_attn<<<dim3(16, 32), 256, FLASH_SMEM>>>(Q, K, V, O);

    // output projection (final fp32 output, no rounding)
    gemm_tc<<<dim3(8, 32), 256, GEMM_SMEM>>>(O, D_, Wor, D_, out, D_, D_, 1.0f, 0);
}

// round 7
// speedup vs baseline: 1.5022x; 1.5022x over previous
#include <cuda_runtime.h>
#include <cuda_fp16.h>
#include <cstdint>
#include <math.h>

#define B_   2
#define T_   2048
#define D_   2048
#define NH   16
#define NKV  8
#define HD   128
#define KVD  1024
#define BT   4096

// ---------------- scratch (device globals; allocation-free) ----------------
__device__ __half g_xh [(size_t)BT  * D_ ];
__device__ __half g_Wqh[(size_t)D_  * D_ ];
__device__ __half g_Wkh[(size_t)KVD * D_ ];
__device__ __half g_Wvh[(size_t)KVD * D_ ];
__device__ __half g_Woh[(size_t)D_  * D_ ];
__device__ __half g_Oh [(size_t)BT  * D_ ];
__device__ float  g_Q  [(size_t)BT  * D_ ];
__device__ float  g_K  [(size_t)BT  * KVD];
__device__ float  g_V  [(size_t)BT  * KVD];

// ---------------- helpers ----------------
__device__ __forceinline__ uint32_t smem_u32(const void* p) {
    uint32_t a;
    asm("{ .reg .u64 t; cvta.to.shared.u64 t, %1; cvt.u32.u64 %0, t; }" : "=r"(a) : "l"(p));
    return a;
}
__device__ __forceinline__ float rtf32(float x) {
    uint32_t r; asm("cvt.rna.tf32.f32 %0, %1;" : "=r"(r) : "f"(x));
    return __uint_as_float(r);
}
__device__ __forceinline__ void cpa16(uint32_t dst, const void* src) {
    asm volatile("cp.async.cg.shared.global [%0], [%1], 16;" :: "r"(dst), "l"(src) : "memory");
}
__device__ __forceinline__ void mma_tf32(float* c, const uint32_t* a, const uint32_t* b) {
    asm volatile("mma.sync.aligned.m16n8k8.row.col.f32.tf32.tf32.f32 "
        "{%0,%1,%2,%3}, {%4,%5,%6,%7}, {%8,%9}, {%0,%1,%2,%3};"
        : "+f"(c[0]), "+f"(c[1]), "+f"(c[2]), "+f"(c[3])
        : "r"(a[0]), "r"(a[1]), "r"(a[2]), "r"(a[3]), "r"(b[0]), "r"(b[1]));
}
__device__ __forceinline__ void mma_f16(float* c, const uint32_t* a, const uint32_t* b) {
    asm volatile("mma.sync.aligned.m16n8k16.row.col.f32.f16.f16.f32 "
        "{%0,%1,%2,%3}, {%4,%5,%6,%7}, {%8,%9}, {%0,%1,%2,%3};"
        : "+f"(c[0]), "+f"(c[1]), "+f"(c[2]), "+f"(c[3])
        : "r"(a[0]), "r"(a[1]), "r"(a[2]), "r"(a[3]), "r"(b[0]), "r"(b[1]));
}

// ---------------------------------------------------------------------------
// fp16 MMA GEMM tile: C[128,128] = alpha * A @ B^T (A, B half, K-contiguous)
// K-chunk 32 halves, 4-stage cp.async, one barrier per chunk.
// 8 warps (2x4), warp tile 64x32.  smem rows padded to 40 halves (bank-free).
// ---------------------------------------------------------------------------
#define HROW 40
#define HBUF (128 * HROW)                  // halves per tile-stage
#define GEMM_SMEM (4 * 2 * HBUF * 2)       // 81920 bytes

__device__ __forceinline__ void gemm_f16_body(
    const __half* __restrict__ A, int lda,
    const __half* __restrict__ B, int ldb,
    float* __restrict__ C, int ldc,
    int K, float alpha, bool round_out, int m0, int n0)
{
    extern __shared__ __half hsm[];
    __half* As = hsm;                // 4 * 5120 halves
    __half* Bs = hsm + 4 * HBUF;

    const int tid  = threadIdx.x;
    const int lane = tid & 31;
    const int w    = tid >> 5;
    const int g    = lane >> 2;
    const int tg   = lane & 3;
    const int wm   = (w >> 2) << 6;    // 0 / 64
    const int wn   = (w & 3)  << 5;    // 0/32/64/96

    float acc[4][4][4];
    #pragma unroll
    for (int i = 0; i < 4; ++i)
        #pragma unroll
        for (int j = 0; j < 4; ++j)
            #pragma unroll
            for (int r = 0; r < 4; ++r)
                acc[i][j][r] = 0.0f;

    const __half* Ab = A + (size_t)m0 * lda;
    const __half* Bb = B + (size_t)n0 * ldb;
    const int nk = K >> 5;             // 32-halves chunks

    // per tile-stage: 128 rows x 32 halves = 512 x 16B; 2 transfers/thread/array
    const int r0 = tid >> 2, s0 = (tid & 3) << 3;      // seg in halves
    const int r1 = (tid + 256) >> 2;

    auto load_chunk = [&](int chunk) {
        const int st = chunk & 3;
        const int kt = chunk << 5;
        uint32_t aD = smem_u32(As + st * HBUF);
        uint32_t bD = smem_u32(Bs + st * HBUF);
        cpa16(aD + (r0 * HROW + s0) * 2, Ab + (size_t)r0 * lda + kt + s0);
        cpa16(bD + (r0 * HROW + s0) * 2, Bb + (size_t)r0 * ldb + kt + s0);
        cpa16(aD + (r1 * HROW + s0) * 2, Ab + (size_t)r1 * lda + kt + s0);
        cpa16(bD + (r1 * HROW + s0) * 2, Bb + (size_t)r1 * ldb + kt + s0);
        asm volatile("cp.async.commit_group;" ::: "memory");
    };

    load_chunk(0);
    if (nk > 1) load_chunk(1);
    if (nk > 2) load_chunk(2);

    for (int i = 0; i < nk; ++i) {
        const int st = i & 3;
        const int rem = nk - 1 - i;
        if (rem >= 2)      asm volatile("cp.async.wait_group 2;" ::: "memory");
        else if (rem == 1) asm volatile("cp.async.wait_group 1;" ::: "memory");
        else               asm volatile("cp.async.wait_group 0;" ::: "memory");
        __syncthreads();
        if (i + 3 < nk) load_chunk(i + 3);

        const __half* Ac = As + st * HBUF;
        const __half* Bc = Bs + st * HBUF;
        #pragma unroll
        for (int ks = 0; ks < 2; ++ks) {         // two k16 steps per chunk
            const int k0 = ks << 4;
            uint32_t bf[4][2];
            #pragma unroll
            for (int nt = 0; nt < 4; ++nt) {
                const __half* br = Bc + (wn + (nt << 3) + g) * HROW + k0 + 2 * tg;
                bf[nt][0] = *(const uint32_t*)(br);
                bf[nt][1] = *(const uint32_t*)(br + 8);
            }
            #pragma unroll
            for (int mt = 0; mt < 4; ++mt) {
                const __half* ar = Ac + (wm + (mt << 4) + g) * HROW + k0 + 2 * tg;
                uint32_t af[4];
                af[0] = *(const uint32_t*)(ar);
                af[1] = *(const uint32_t*)(ar + 8 * HROW);
                af[2] = *(const uint32_t*)(ar + 8);
                af[3] = *(const uint32_t*)(ar + 8 * HROW + 8);
                #pragma unroll
                for (int nt = 0; nt < 4; ++nt)
                    mma_f16(acc[mt][nt], af, bf[nt]);
            }
        }
    }

    #pragma unroll
    for (int mt = 0; mt < 4; ++mt) {
        const int rr = m0 + wm + (mt << 4) + g;
        #pragma unroll
        for (int nt = 0; nt < 4; ++nt) {
            const int cb = n0 + wn + (nt << 3) + (tg << 1);
            float2 v0, v1;
            v0.x = acc[mt][nt][0] * alpha;  v0.y = acc[mt][nt][1] * alpha;
            v1.x = acc[mt][nt][2] * alpha;  v1.y = acc[mt][nt][3] * alpha;
            if (round_out) {
                v0.x = rtf32(v0.x); v0.y = rtf32(v0.y);
                v1.x = rtf32(v1.x); v1.y = rtf32(v1.y);
            }
            *(float2*)(C + (size_t)rr * ldc + cb)       = v0;
            *(float2*)(C + (size_t)(rr + 8) * ldc + cb) = v1;
        }
    }
}

// fused QKV projection: bx 0..15 -> Q, 16..23 -> K, 24..31 -> V
__global__ void __launch_bounds__(256, 2)
qkv_proj(const __half* __restrict__ xh,
         const __half* __restrict__ Wq, const __half* __restrict__ Wk,
         const __half* __restrict__ Wv,
         float* __restrict__ Q, float* __restrict__ K, float* __restrict__ V)
{
    const int bx = blockIdx.x;
    const __half* Bp;  float* Cp;  int ldc, n0;
    if (bx < 16)      { Bp = Wq; Cp = Q; ldc = D_;  n0 = bx * 128; }
    else if (bx < 24) { Bp = Wk; Cp = K; ldc = KVD; n0 = (bx - 16) * 128; }
    else              { Bp = Wv; Cp = V; ldc = KVD; n0 = (bx - 24) * 128; }
    gemm_f16_body(xh, D_, Bp, D_, Cp, ldc, D_, 1.0f, true, blockIdx.y * 128, n0);
}

__global__ void __launch_bounds__(256, 2)
out_proj(const __half* __restrict__ Oh, const __half* __restrict__ Wo,
         float* __restrict__ out)
{
    gemm_f16_body(Oh, D_, Wo, D_, out, D_, D_, 1.0f, false,
                  blockIdx.y * 128, blockIdx.x * 128);
}

// ---------------------------------------------------------------------------
// Flash attention (tf32, proven) — epilogue now writes half O for out_proj.
// ---------------------------------------------------------------------------
#define SK_STRIDE 132
#define SV_STRIDE 136
#define SP_STRIDE 68
#define SK_BUF (64 * SK_STRIDE)
#define SV_BUF (64 * SV_STRIDE)
#define FLASH_SMEM ((2*SK_BUF + 2*SV_BUF + 8*16*SP_STRIDE) * 4)

__global__ void __launch_bounds__(256, 1)
flash_attn(const float* __restrict__ Qg, const float* __restrict__ Kg,
           const float* __restrict__ Vg, __half* __restrict__ Og)
{
    extern __shared__ float fsm[];
    float* sK = fsm;
    float* sV = fsm + 2 * SK_BUF;
    float* sP = fsm + 2 * SK_BUF + 2 * SV_BUF;

    const int tid  = threadIdx.x;
    const int lane = tid & 31;
    const int w    = tid >> 5;
    const int g    = lane >> 2;
    const int tg   = lane & 3;
    const int z    = blockIdx.y, b = z >> 4, hq = z & 15, kv = hq >> 1;
    const int m0   = blockIdx.x << 7;
    const float inv_scale = 0.088388347648318447f;

    const size_t qbase = (size_t)b * T_ * D_  + (size_t)hq * HD;
    const size_t kbase = (size_t)b * T_ * KVD + (size_t)kv * HD;

    #pragma unroll
    for (int j = 0; j < 16; ++j) {
        int u = tid + (j << 8);
        int row = u >> 5, seg = (u & 31) << 2;
        cpa16(smem_u32(sK + row * SK_STRIDE + seg),
              Qg + qbase + (size_t)(m0 + row) * D_ + seg);
    }
    asm volatile("cp.async.commit_group;" ::: "memory");
    asm volatile("cp.async.wait_group 0;" ::: "memory");
    __syncthreads();

    uint32_t qf[16][4];
    {
        const float* qr0 = sK + (w * 16 + g) * SK_STRIDE;
        const float* qr1 = qr0 + 8 * SK_STRIDE;
        #pragma unroll
        for (int ks = 0; ks < 16; ++ks) {
            qf[ks][0] = __float_as_uint(rtf32(qr0[ks * 8 + tg]     * inv_scale));
            qf[ks][1] = __float_as_uint(rtf32(qr1[ks * 8 + tg]     * inv_scale));
            qf[ks][2] = __float_as_uint(rtf32(qr0[ks * 8 + tg + 4] * inv_scale));
            qf[ks][3] = __float_as_uint(rtf32(qr1[ks * 8 + tg + 4] * inv_scale));
        }
    }
    __syncthreads();

    float of[16][4];
    #pragma unroll
    for (int nt = 0; nt < 16; ++nt)
        #pragma unroll
        for (int r = 0; r < 4; ++r)
            of[nt][r] = 0.0f;
    float mprev0 = -1e30f, mprev1 = -1e30f, l0 = 0.0f, l1 = 0.0f;

    #pragma unroll
    for (int j = 0; j < 8; ++j) {
        int u = tid + (j << 8);
        int row = u >> 5, seg = (u & 31) << 2;
        cpa16(smem_u32(sK + row * SK_STRIDE + seg), Kg + kbase + (size_t)row * KVD + seg);
        cpa16(smem_u32(sV + row * SV_STRIDE + seg), Vg + kbase + (size_t)row * KVD + seg);
    }
    asm volatile("cp.async.commit_group;" ::: "memory");

    float* Pw = sP + w * 16 * SP_STRIDE;

    for (int it = 0; it < 32; ++it) {
        const int buf = it & 1;
        if (it + 1 < 32) {
            const int nb = buf ^ 1;
            const int t0 = (it + 1) << 6;
            #pragma unroll
            for (int j = 0; j < 8; ++j) {
                int u = tid + (j << 8);
                int row = u >> 5, seg = (u & 31) << 2;
                cpa16(smem_u32(sK + nb * SK_BUF + row * SK_STRIDE + seg),
                      Kg + kbase + (size_t)(t0 + row) * KVD + seg);
                cpa16(smem_u32(sV + nb * SV_BUF + row * SV_STRIDE + seg),
                      Vg + kbase + (size_t)(t0 + row) * KVD + seg);
            }
            asm volatile("cp.async.commit_group;" ::: "memory");
            asm volatile("cp.async.wait_group 1;" ::: "memory");
        } else {
            asm volatile("cp.async.wait_group 0;" ::: "memory");
        }
        __syncthreads();

        const float* Kb = sK + buf * SK_BUF;
        const float* Vb = sV + buf * SV_BUF;

        float sf[8][4];
        #pragma unroll
        for (int nt = 0; nt < 8; ++nt)
            sf[nt][0] = sf[nt][1] = sf[nt][2] = sf[nt][3] = 0.0f;
        #pragma unroll
        for (int ks = 0; ks < 16; ++ks) {
            const int k0 = ks << 3;
            #pragma unroll
            for (int nt = 0; nt < 8; ++nt) {
                uint32_t bb[2];
                const float* kr = Kb + (nt * 8 + g) * SK_STRIDE + k0;
                bb[0] = __float_as_uint(kr[tg]);
                bb[1] = __float_as_uint(kr[tg + 4]);
                mma_tf32(sf[nt], qf[ks], bb);
            }
        }

        float mx0 = mprev0, mx1 = mprev1;
        #pragma unroll
        for (int nt = 0; nt < 8; ++nt) {
            mx0 = fmaxf(mx0, fmaxf(sf[nt][0], sf[nt][1]));
            mx1 = fmaxf(mx1, fmaxf(sf[nt][2], sf[nt][3]));
        }
        mx0 = fmaxf(mx0, __shfl_xor_sync(0xffffffffu, mx0, 1));
        mx0 = fmaxf(mx0, __shfl_xor_sync(0xffffffffu, mx0, 2));
        mx1 = fmaxf(mx1, __shfl_xor_sync(0xffffffffu, mx1, 1));
        mx1 = fmaxf(mx1, __shfl_xor_sync(0xffffffffu, mx1, 2));

        const float sc0 = __expf(mprev0 - mx0);
        const float sc1 = __expf(mprev1 - mx1);
        mprev0 = mx0; mprev1 = mx1;

        float rs0 = 0.0f, rs1 = 0.0f;
        #pragma unroll
        for (int nt = 0; nt < 8; ++nt) {
            float p0 = __expf(sf[nt][0] - mx0);
            float p1 = __expf(sf[nt][1] - mx0);
            float p2 = __expf(sf[nt][2] - mx1);
            float p3 = __expf(sf[nt][3] - mx1);
            rs0 += p0 + p1;  rs1 += p2 + p3;
            float2 st0 = make_float2(rtf32(p0), rtf32(p1));
            float2 st1 = make_float2(rtf32(p2), rtf32(p3));
            *(float2*)(Pw + g * SP_STRIDE + nt * 8 + 2 * tg)       = st0;
            *(float2*)(Pw + (g + 8) * SP_STRIDE + nt * 8 + 2 * tg) = st1;
        }
        rs0 += __shfl_xor_sync(0xffffffffu, rs0, 1);
        rs0 += __shfl_xor_sync(0xffffffffu, rs0, 2);
        rs1 += __shfl_xor_sync(0xffffffffu, rs1, 1);
        rs1 += __shfl_xor_sync(0xffffffffu, rs1, 2);
        l0 = l0 * sc0 + rs0;
        l1 = l1 * sc1 + rs1;

        #pragma unroll
        for (int nt = 0; nt < 16; ++nt) {
            of[nt][0] *= sc0; of[nt][1] *= sc0;
            of[nt][2] *= sc1; of[nt][3] *= sc1;
        }
        __syncwarp();

        #pragma unroll
        for (int kc = 0; kc < 8; ++kc) {
            uint32_t aa[4];
            const float* pr0 = Pw + g * SP_STRIDE + kc * 8;
            const float* pr1 = Pw + (g + 8) * SP_STRIDE + kc * 8;
            aa[0] = __float_as_uint(pr0[tg]);
            aa[1] = __float_as_uint(pr1[tg]);
            aa[2] = __float_as_uint(pr0[tg + 4]);
            aa[3] = __float_as_uint(pr1[tg + 4]);
            const float* vr0 = Vb + (kc * 8 + tg) * SV_STRIDE + g;
            const float* vr1 = Vb + (kc * 8 + tg + 4) * SV_STRIDE + g;
            #pragma unroll
            for (int nt = 0; nt < 16; ++nt) {
                uint32_t bb[2];
                bb[0] = __float_as_uint(vr0[nt * 8]);
                bb[1] = __float_as_uint(vr1[nt * 8]);
                mma_tf32(of[nt], aa, bb);
            }
        }
        __syncthreads();
    }

    // epilogue: O /= l, store half (rounding for the fp16 out-proj)
    const float i0 = 1.0f / l0;
    const float i1 = 1.0f / l1;
    const int r0 = m0 + w * 16 + g;
    const size_t obase = (size_t)b * T_ * D_ + (size_t)hq * HD;
    #pragma unroll
    for (int nt = 0; nt < 16; ++nt) {
        const int c = nt * 8 + 2 * tg;
        __half2 h0 = __floats2half2_rn(of[nt][0] * i0, of[nt][1] * i0);
        __half2 h1 = __floats2half2_rn(of[nt][2] * i1, of[nt][3] * i1);
        *(__half2*)(Og + obase + (size_t)r0 * D_ + c)       = h0;
        *(__half2*)(Og + obase + (size_t)(r0 + 8) * D_ + c) = h1;
    }
}

// convert fp32 -> fp16 (round to nearest), vectorized
__global__ void __launch_bounds__(256)
to_half(const float4* __restrict__ in, uint2* __restrict__ out, int n4)
{
    int i = blockIdx.x * blockDim.x + threadIdx.x;
    int stride = gridDim.x * blockDim.x;
    for (; i < n4; i += stride) {
        float4 v = in[i];
        __half2 h0 = __floats2half2_rn(v.x, v.y);
        __half2 h1 = __floats2half2_rn(v.z, v.w);
        uint2 r;
        r.x = *(uint32_t*)&h0;
        r.y = *(uint32_t*)&h1;
        out[i] = r;
    }
}

// ---------------- host ----------------
extern "C" void kernel_launch(void* const* d_in, const int* in_sizes, int n_in,
                              void* d_out, int out_size)
{
    (void)in_sizes; (void)n_in; (void)out_size;
    const float* x  = (const float*)d_in[0];
    const float* Wq = (const float*)d_in[1];
    const float* Wk = (const float*)d_in[2];
    const float* Wv = (const float*)d_in[3];
    const float* Wo = (const float*)d_in[4];
    float* out = (float*)d_out;

    __half *xh, *Wqh, *Wkh, *Wvh, *Woh, *Oh;
    float *Q, *K, *V;
    cudaGetSymbolAddress((void**)&xh,  g_xh);
    cudaGetSymbolAddress((void**)&Wqh, g_Wqh);
    cudaGetSymbolAddress((void**)&Wkh, g_Wkh);
    cudaGetSymbolAddress((void**)&Wvh, g_Wvh);
    cudaGetSymbolAddress((void**)&Woh, g_Woh);
    cudaGetSymbolAddress((void**)&Oh,  g_Oh);
    cudaGetSymbolAddress((void**)&Q,   g_Q);
    cudaGetSymbolAddress((void**)&K,   g_K);
    cudaGetSymbolAddress((void**)&V,   g_V);

    cudaFuncSetAttribute(qkv_proj, cudaFuncAttributeMaxDynamicSharedMemorySize,
                         GEMM_SMEM);
    cudaFuncSetAttribute(out_proj, cudaFuncAttributeMaxDynamicSharedMemorySize,
                         GEMM_SMEM);
    cudaFuncSetAttribute(flash_attn, cudaFuncAttributeMaxDynamicSharedMemorySize,
                         FLASH_SMEM);

    // convert all GEMM operands to fp16 (rn)
    to_half<<<1024, 256>>>((const float4*)x,  (uint2*)xh,  BT  * D_  / 4);
    to_half<<<1024, 256>>>((const float4*)Wq, (uint2*)Wqh, D_  * D_  / 4);
    to_half<<<1024, 256>>>((const float4*)Wk, (uint2*)Wkh, KVD * D_  / 4);
    to_half<<<1024, 256>>>((const float4*)Wv, (uint2*)Wvh, KVD * D_  / 4);
    to_half<<<1024, 256>>>((const float4*)Wo, (uint2*)Woh, D_  * D_  / 4);

    // fused Q/K/V projections (fp16 MMA; float outputs tf32-rounded for flash)
    qkv_proj<<<dim3(32, 32), 256, GEMM_SMEM>>>(xh, Wqh, Wkh, Wvh, Q, K, V);

    // fused attention (tf32; writes half O)
    flash_attn<<<dim3(16, 32), 256, FLASH_SMEM>>>(Q, K, V, Oh);

    // output projection (fp16 MMA; final fp32 output)
    out_proj<<<dim3(16, 32), 256, GEMM_SMEM>>>(Oh, Woh, out);
}

// round 8
// speedup vs baseline: 1.9956x; 1.3284x over previous
#include <cuda_runtime.h>
#include <cuda_fp16.h>
#include <cstdint>
#include <math.h>

#define B_   2
#define T_   2048
#define D_   2048
#define NH   16
#define NKV  8
#define HD   128
#define KVD  1024
#define BT   4096

// ---------------- scratch (device globals; allocation-free) ----------------
__device__ __half g_xh [(size_t)BT  * D_ ];
__device__ __half g_Wqh[(size_t)D_  * D_ ];
__device__ __half g_Wkh[(size_t)KVD * D_ ];
__device__ __half g_Wvh[(size_t)KVD * D_ ];
__device__ __half g_Woh[(size_t)D_  * D_ ];
__device__ __half g_Qh [(size_t)BT  * D_ ];
__device__ __half g_Kh [(size_t)BT  * KVD];
__device__ __half g_Vh [(size_t)BT  * KVD];
__device__ __half g_Vth[(size_t)BT  * KVD];   // [b][d(1024)][t(2048)]
__device__ __half g_Oh [(size_t)BT  * D_ ];

// ---------------- helpers ----------------
__device__ __forceinline__ uint32_t smem_u32(const void* p) {
    uint32_t a;
    asm("{ .reg .u64 t; cvta.to.shared.u64 t, %1; cvt.u32.u64 %0, t; }" : "=r"(a) : "l"(p));
    return a;
}
__device__ __forceinline__ void cpa16(uint32_t dst, const void* src) {
    asm volatile("cp.async.cg.shared.global [%0], [%1], 16;" :: "r"(dst), "l"(src) : "memory");
}
__device__ __forceinline__ void mma_f16(float* c, const uint32_t* a, const uint32_t* b) {
    asm volatile("mma.sync.aligned.m16n8k16.row.col.f32.f16.f16.f32 "
        "{%0,%1,%2,%3}, {%4,%5,%6,%7}, {%8,%9}, {%0,%1,%2,%3};"
        : "+f"(c[0]), "+f"(c[1]), "+f"(c[2]), "+f"(c[3])
        : "r"(a[0]), "r"(a[1]), "r"(a[2]), "r"(a[3]), "r"(b[0]), "r"(b[1]));
}

// ---------------------------------------------------------------------------
// fp16 MMA GEMM tile: C[128,128] = A @ B^T (half, K-contiguous), 4-stage.
// ---------------------------------------------------------------------------
#define HROW 40
#define HBUF (128 * HROW)
#define GEMM_SMEM (4 * 2 * HBUF * 2)       // 81920 bytes

template<bool HALF_OUT>
__device__ __forceinline__ void gemm_f16_body(
    const __half* __restrict__ A, int lda,
    const __half* __restrict__ B, int ldb,
    void* __restrict__ Cv, int ldc,
    int K, int m0, int n0)
{
    extern __shared__ __half hsm[];
    __half* As = hsm;
    __half* Bs = hsm + 4 * HBUF;

    const int tid  = threadIdx.x;
    const int lane = tid & 31;
    const int w    = tid >> 5;
    const int g    = lane >> 2;
    const int tg   = lane & 3;
    const int wm   = (w >> 2) << 6;
    const int wn   = (w & 3)  << 5;

    float acc[4][4][4];
    #pragma unroll
    for (int i = 0; i < 4; ++i)
        #pragma unroll
        for (int j = 0; j < 4; ++j)
            #pragma unroll
            for (int r = 0; r < 4; ++r)
                acc[i][j][r] = 0.0f;

    const __half* Ab = A + (size_t)m0 * lda;
    const __half* Bb = B + (size_t)n0 * ldb;
    const int nk = K >> 5;

    const int r0 = tid >> 2, s0 = (tid & 3) << 3;
    const int r1 = (tid + 256) >> 2;

    auto load_chunk = [&](int chunk) {
        const int st = chunk & 3;
        const int kt = chunk << 5;
        uint32_t aD = smem_u32(As + st * HBUF);
        uint32_t bD = smem_u32(Bs + st * HBUF);
        cpa16(aD + (r0 * HROW + s0) * 2, Ab + (size_t)r0 * lda + kt + s0);
        cpa16(bD + (r0 * HROW + s0) * 2, Bb + (size_t)r0 * ldb + kt + s0);
        cpa16(aD + (r1 * HROW + s0) * 2, Ab + (size_t)r1 * lda + kt + s0);
        cpa16(bD + (r1 * HROW + s0) * 2, Bb + (size_t)r1 * ldb + kt + s0);
        asm volatile("cp.async.commit_group;" ::: "memory");
    };

    load_chunk(0);
    if (nk > 1) load_chunk(1);
    if (nk > 2) load_chunk(2);

    for (int i = 0; i < nk; ++i) {
        const int st = i & 3;
        const int rem = nk - 1 - i;
        if (rem >= 2)      asm volatile("cp.async.wait_group 2;" ::: "memory");
        else if (rem == 1) asm volatile("cp.async.wait_group 1;" ::: "memory");
        else               asm volatile("cp.async.wait_group 0;" ::: "memory");
        __syncthreads();
        if (i + 3 < nk) load_chunk(i + 3);

        const __half* Ac = As + st * HBUF;
        const __half* Bc = Bs + st * HBUF;
        #pragma unroll
        for (int ks = 0; ks < 2; ++ks) {
            const int k0 = ks << 4;
            uint32_t bf[4][2];
            #pragma unroll
            for (int nt = 0; nt < 4; ++nt) {
                const __half* br = Bc + (wn + (nt << 3) + g) * HROW + k0 + 2 * tg;
                bf[nt][0] = *(const uint32_t*)(br);
                bf[nt][1] = *(const uint32_t*)(br + 8);
            }
            #pragma unroll
            for (int mt = 0; mt < 4; ++mt) {
                const __half* ar = Ac + (wm + (mt << 4) + g) * HROW + k0 + 2 * tg;
                uint32_t af[4];
                af[0] = *(const uint32_t*)(ar);
                af[1] = *(const uint32_t*)(ar + 8 * HROW);
                af[2] = *(const uint32_t*)(ar + 8);
                af[3] = *(const uint32_t*)(ar + 8 * HROW + 8);
                #pragma unroll
                for (int nt = 0; nt < 4; ++nt)
                    mma_f16(acc[mt][nt], af, bf[nt]);
            }
        }
    }

    #pragma unroll
    for (int mt = 0; mt < 4; ++mt) {
        const int rr = m0 + wm + (mt << 4) + g;
        #pragma unroll
        for (int nt = 0; nt < 4; ++nt) {
            const int cb = n0 + wn + (nt << 3) + (tg << 1);
            if (HALF_OUT) {
                __half* C = (__half*)Cv;
                *(__half2*)(C + (size_t)rr * ldc + cb) =
                    __floats2half2_rn(acc[mt][nt][0], acc[mt][nt][1]);
                *(__half2*)(C + (size_t)(rr + 8) * ldc + cb) =
                    __floats2half2_rn(acc[mt][nt][2], acc[mt][nt][3]);
            } else {
                float* C = (float*)Cv;
                *(float2*)(C + (size_t)rr * ldc + cb) =
                    make_float2(acc[mt][nt][0], acc[mt][nt][1]);
                *(float2*)(C + (size_t)(rr + 8) * ldc + cb) =
                    make_float2(acc[mt][nt][2], acc[mt][nt][3]);
            }
        }
    }
}

// fused QKV projection: bx 0..15 -> Q, 16..23 -> K, 24..31 -> V (half outputs)
__global__ void __launch_bounds__(256, 2)
qkv_proj(const __half* __restrict__ xh,
         const __half* __restrict__ Wq, const __half* __restrict__ Wk,
         const __half* __restrict__ Wv,
         __half* __restrict__ Q, __half* __restrict__ K, __half* __restrict__ V)
{
    const int bx = blockIdx.x;
    const __half* Bp;  __half* Cp;  int ldc, n0;
    if (bx < 16)      { Bp = Wq; Cp = Q; ldc = D_;  n0 = bx * 128; }
    else if (bx < 24) { Bp = Wk; Cp = K; ldc = KVD; n0 = (bx - 16) * 128; }
    else              { Bp = Wv; Cp = V; ldc = KVD; n0 = (bx - 24) * 128; }
    gemm_f16_body<true>(xh, D_, Bp, D_, Cp, ldc, D_, blockIdx.y * 128, n0);
}

__global__ void __launch_bounds__(256, 2)
out_proj(const __half* __restrict__ Oh, const __half* __restrict__ Wo,
         float* __restrict__ out)
{
    gemm_f16_body<false>(Oh, D_, Wo, D_, out, D_, D_,
                         blockIdx.y * 128, blockIdx.x * 128);
}

// half transpose: Vh[b][t][n] -> Vth[b][n][t], 64x64 tiles
__global__ void __launch_bounds__(256)
transpose_vh(const __half* __restrict__ V, __half* __restrict__ Vt)
{
    __shared__ __half tile[64][66];
    const int b  = blockIdx.z;
    const int t0 = blockIdx.x << 6, n0 = blockIdx.y << 6;
    const int tx = threadIdx.x & 31, ty = threadIdx.x >> 5;
    const __half* src = V  + (size_t)b * T_ * KVD;
    __half*       dst = Vt + (size_t)b * KVD * T_;
    #pragma unroll
    for (int j = 0; j < 8; ++j) {
        int r = ty + (j << 3);
        __half2 h = *(const __half2*)(src + (size_t)(t0 + r) * KVD + n0 + 2 * tx);
        tile[2 * tx][r]     = __low2half(h);
        tile[2 * tx + 1][r] = __high2half(h);
    }
    __syncthreads();
    #pragma unroll
    for (int j = 0; j < 8; ++j) {
        int r = ty + (j << 3);
        __half2 h = __halves2half2(tile[r][2 * tx], tile[r][2 * tx + 1]);
        *(__half2*)(dst + (size_t)(n0 + r) * T_ + t0 + 2 * tx) = h;
    }
}

// ---------------------------------------------------------------------------
// fp16 flash attention: CTA = 128 q-rows x one (b,hq). 8 warps x 16 rows.
// smem (halves): sK[2][64][136] (Q staged over both bufs), sVt[2][128][72],
// sP[8][16][72].  Total 90112 B.
// ---------------------------------------------------------------------------
#define SKH 136
#define SVH 72
#define SPH 72
#define SKB (64 * SKH)     // 8704 halves
#define SVB (128 * SVH)    // 9216 halves
#define FLASH_SMEM ((2*SKB + 2*SVB + 8*16*SPH) * 2)   // 90112 B

__global__ void __launch_bounds__(256, 1)
flash_attn(const __half* __restrict__ Qg, const __half* __restrict__ Kg,
           const __half* __restrict__ Vtg, __half* __restrict__ Og)
{
    extern __shared__ __half hsm[];
    __half* sK  = hsm;
    __half* sVt = hsm + 2 * SKB;
    __half* sP  = hsm + 2 * SKB + 2 * SVB;

    const int tid  = threadIdx.x;
    const int lane = tid & 31;
    const int w    = tid >> 5;
    const int g    = lane >> 2;
    const int tg   = lane & 3;
    const int z    = blockIdx.y, b = z >> 4, hq = z & 15, kv = hq >> 1;
    const int m0   = blockIdx.x << 7;
    const float inv_scale = 0.088388347648318447f;

    const size_t qbase  = (size_t)b * T_ * D_  + (size_t)hq * HD;
    const size_t kbase  = (size_t)b * T_ * KVD + (size_t)kv * HD;
    const size_t vtbase = ((size_t)b * KVD + (size_t)kv * HD) * T_;

    // ---- stage Q tile (128 x 128 halves) into sK region, stride SKH
    #pragma unroll
    for (int j = 0; j < 8; ++j) {
        int u = tid + (j << 8);
        int row = u >> 4, seg = (u & 15) << 3;
        cpa16(smem_u32(sK + row * SKH + seg) ,
              Qg + qbase + (size_t)(m0 + row) * D_ + seg);
    }
    asm volatile("cp.async.commit_group;" ::: "memory");
    asm volatile("cp.async.wait_group 0;" ::: "memory");
    __syncthreads();

    // Q fragments (scaled in fp32, rounded to half)
    uint32_t qf[8][4];
    {
        const __half* qr0 = sK + (w * 16 + g) * SKH;
        const __half* qr1 = qr0 + 8 * SKH;
        #pragma unroll
        for (int ks = 0; ks < 8; ++ks) {
            const int c = (ks << 4) + 2 * tg;
            #pragma unroll
            for (int h = 0; h < 2; ++h) {       // h=0: cols c, c+1 ; h=1: +8
                const int cc = c + h * 8;
                __half2 a0 = *(const __half2*)(qr0 + cc);
                __half2 a1 = *(const __half2*)(qr1 + cc);
                __half2 s0 = __floats2half2_rn(__low2float(a0) * inv_scale,
                                               __high2float(a0) * inv_scale);
                __half2 s1 = __floats2half2_rn(__low2float(a1) * inv_scale,
                                               __high2float(a1) * inv_scale);
                qf[ks][h * 2]     = *(uint32_t*)&s0;
                qf[ks][h * 2 + 1] = *(uint32_t*)&s1;
            }
        }
        // reorder to fragment order: af = {r0lo, r1lo, r0hi, r1hi}
        #pragma unroll
        for (int ks = 0; ks < 8; ++ks) {
            uint32_t t1 = qf[ks][1], t2 = qf[ks][2];
            qf[ks][1] = qf[ks][1]; // a[1] = row g+8 low  (already at [1]? fix below)
            qf[ks][2] = t2;
        }
    }
    __syncthreads();

    float of[16][4];
    #pragma unroll
    for (int nt = 0; nt < 16; ++nt)
        #pragma unroll
        for (int r = 0; r < 4; ++r)
            of[nt][r] = 0.0f;
    float mprev0 = -1e30f, mprev1 = -1e30f, l0 = 0.0f, l1 = 0.0f;

    // stage kv iter 0: K 64x128, Vt 128x64
    #pragma unroll
    for (int j = 0; j < 4; ++j) {
        int u = tid + (j << 8);
        int kr = u >> 4, ks_ = (u & 15) << 3;
        cpa16(smem_u32(sK + kr * SKH + ks_), Kg + kbase + (size_t)kr * KVD + ks_);
        int vr = u >> 3, vs = (u & 7) << 3;
        cpa16(smem_u32(sVt + vr * SVH + vs), Vtg + vtbase + (size_t)vr * T_ + vs);
    }
    asm volatile("cp.async.commit_group;" ::: "memory");

    __half* Pw = sP + w * 16 * SPH;

    for (int it = 0; it < 32; ++it) {
        const int buf = it & 1;
        if (it + 1 < 32) {
            const int nb = buf ^ 1;
            const int t0 = (it + 1) << 6;
            #pragma unroll
            for (int j = 0; j < 4; ++j) {
                int u = tid + (j << 8);
                int kr = u >> 4, ks_ = (u & 15) << 3;
                cpa16(smem_u32(sK + nb * SKB + kr * SKH + ks_),
                      Kg + kbase + (size_t)(t0 + kr) * KVD + ks_);
                int vr = u >> 3, vs = (u & 7) << 3;
                cpa16(smem_u32(sVt + nb * SVB + vr * SVH + vs),
                      Vtg + vtbase + (size_t)vr * T_ + t0 + vs);
            }
            asm volatile("cp.async.commit_group;" ::: "memory");
            asm volatile("cp.async.wait_group 1;" ::: "memory");
        } else {
            asm volatile("cp.async.wait_group 0;" ::: "memory");
        }
        __syncthreads();

        const __half* Kb  = sK  + buf * SKB;
        const __half* Vtb = sVt + buf * SVB;

        // S = Q @ K^T  (16 x 64 per warp, fp16 k16)
        float sf[8][4];
        #pragma unroll
        for (int nt = 0; nt < 8; ++nt)
            sf[nt][0] = sf[nt][1] = sf[nt][2] = sf[nt][3] = 0.0f;
        #pragma unroll
        for (int ks = 0; ks < 8; ++ks) {
            const int k0 = ks << 4;
            #pragma unroll
            for (int nt = 0; nt < 8; ++nt) {
                const __half* br = Kb + (nt * 8 + g) * SKH + k0 + 2 * tg;
                uint32_t bb[2];
                bb[0] = *(const uint32_t*)(br);
                bb[1] = *(const uint32_t*)(br + 8);
                mma_f16(sf[nt], qf[ks], bb);
            }
        }

        // online softmax
        float mx0 = mprev0, mx1 = mprev1;
        #pragma unroll
        for (int nt = 0; nt < 8; ++nt) {
            mx0 = fmaxf(mx0, fmaxf(sf[nt][0], sf[nt][1]));
            mx1 = fmaxf(mx1, fmaxf(sf[nt][2], sf[nt][3]));
        }
        mx0 = fmaxf(mx0, __shfl_xor_sync(0xffffffffu, mx0, 1));
        mx0 = fmaxf(mx0, __shfl_xor_sync(0xffffffffu, mx0, 2));
        mx1 = fmaxf(mx1, __shfl_xor_sync(0xffffffffu, mx1, 1));
        mx1 = fmaxf(mx1, __shfl_xor_sync(0xffffffffu, mx1, 2));

        const float sc0 = __expf(mprev0 - mx0);
        const float sc1 = __expf(mprev1 - mx1);
        mprev0 = mx0; mprev1 = mx1;

        float rs0 = 0.0f, rs1 = 0.0f;
        #pragma unroll
        for (int nt = 0; nt < 8; ++nt) {
            float p0 = __expf(sf[nt][0] - mx0);
            float p1 = __expf(sf[nt][1] - mx0);
            float p2 = __expf(sf[nt][2] - mx1);
            float p3 = __expf(sf[nt][3] - mx1);
            rs0 += p0 + p1;  rs1 += p2 + p3;
            *(__half2*)(Pw + g * SPH + nt * 8 + 2 * tg)       = __floats2half2_rn(p0, p1);
            *(__half2*)(Pw + (g + 8) * SPH + nt * 8 + 2 * tg) = __floats2half2_rn(p2, p3);
        }
        rs0 += __shfl_xor_sync(0xffffffffu, rs0, 1);
        rs0 += __shfl_xor_sync(0xffffffffu, rs0, 2);
        rs1 += __shfl_xor_sync(0xffffffffu, rs1, 1);
        rs1 += __shfl_xor_sync(0xffffffffu, rs1, 2);
        l0 = l0 * sc0 + rs0;
        l1 = l1 * sc1 + rs1;

        #pragma unroll
        for (int nt = 0; nt < 16; ++nt) {
            of[nt][0] *= sc0; of[nt][1] *= sc0;
            of[nt][2] *= sc1; of[nt][3] *= sc1;
        }
        __syncwarp();

        // O += P @ V  (16 x 128 per warp, fp16 k16; V from Vt[d][t])
        #pragma unroll
        for (int kc = 0; kc < 4; ++kc) {
            const int k0 = kc << 4;
            uint32_t aa[4];
            const __half* pr0 = Pw + g * SPH + k0 + 2 * tg;
            const __half* pr1 = Pw + (g + 8) * SPH + k0 + 2 * tg;
            aa[0] = *(const uint32_t*)(pr0);
            aa[1] = *(const uint32_t*)(pr1);
            aa[2] = *(const uint32_t*)(pr0 + 8);
            aa[3] = *(const uint32_t*)(pr1 + 8);
            #pragma unroll
            for (int nt = 0; nt < 16; ++nt) {
                const __half* vr = Vtb + (nt * 8 + g) * SVH + k0 + 2 * tg;
                uint32_t bb[2];
                bb[0] = *(const uint32_t*)(vr);
                bb[1] = *(const uint32_t*)(vr + 8);
                mma_f16(of[nt], aa, bb);
            }
        }
        __syncthreads();
    }

    // epilogue: O /= l, store half (input to fp16 out-proj)
    const float i0 = 1.0f / l0;
    const float i1 = 1.0f / l1;
    const int r0 = m0 + w * 16 + g;
    const size_t obase = (size_t)b * T_ * D_ + (size_t)hq * HD;
    #pragma unroll
    for (int nt = 0; nt < 16; ++nt) {
        const int c = nt * 8 + 2 * tg;
        *(__half2*)(Og + obase + (size_t)r0 * D_ + c) =
            __floats2half2_rn(of[nt][0] * i0, of[nt][1] * i0);
        *(__half2*)(Og + obase + (size_t)(r0 + 8) * D_ + c) =
            __floats2half2_rn(of[nt][2] * i1, of[nt][3] * i1);
    }
}

// convert fp32 -> fp16 (rn), vectorized
__global__ void __launch_bounds__(256)
to_half(const float4* __restrict__ in, uint2* __restrict__ out, int n4)
{
    int i = blockIdx.x * blockDim.x + threadIdx.x;
    int stride = gridDim.x * blockDim.x;
    for (; i < n4; i += stride) {
        float4 v = in[i];
        __half2 h0 = __floats2half2_rn(v.x, v.y);
        __half2 h1 = __floats2half2_rn(v.z, v.w);
        uint2 r;
        r.x = *(uint32_t*)&h0;
        r.y = *(uint32_t*)&h1;
        out[i] = r;
    }
}

// ---------------- host ----------------
extern "C" void kernel_launch(void* const* d_in, const int* in_sizes, int n_in,
                              void* d_out, int out_size)
{
    (void)in_sizes; (void)n_in; (void)out_size;
    const float* x  = (const float*)d_in[0];
    const float* Wq = (const float*)d_in[1];
    const float* Wk = (const float*)d_in[2];
    const float* Wv = (const float*)d_in[3];
    const float* Wo = (const float*)d_in[4];
    float* out = (float*)d_out;

    __half *xh, *Wqh, *Wkh, *Wvh, *Woh, *Qh, *Kh, *Vh, *Vth, *Oh;
    cudaGetSymbolAddress((void**)&xh,  g_xh);
    cudaGetSymbolAddress((void**)&Wqh, g_Wqh);
    cudaGetSymbolAddress((void**)&Wkh, g_Wkh);
    cudaGetSymbolAddress((void**)&Wvh, g_Wvh);
    cudaGetSymbolAddress((void**)&Woh, g_Woh);
    cudaGetSymbolAddress((void**)&Qh,  g_Qh);
    cudaGetSymbolAddress((void**)&Kh,  g_Kh);
    cudaGetSymbolAddress((void**)&Vh,  g_Vh);
    cudaGetSymbolAddress((void**)&Vth, g_Vth);
    cudaGetSymbolAddress((void**)&Oh,  g_Oh);

    cudaFuncSetAttribute(qkv_proj, cudaFuncAttributeMaxDynamicSharedMemorySize,
                         GEMM_SMEM);
    cudaFuncSetAttribute(out_proj, cudaFuncAttributeMaxDynamicSharedMemorySize,
                         GEMM_SMEM);
    cudaFuncSetAttribute(flash_attn, cudaFuncAttributeMaxDynamicSharedMemorySize,
                         FLASH_SMEM);

    // convert inputs to fp16 (rn)
    to_half<<<1024, 256>>>((const float4*)x,  (uint2*)xh,  BT  * D_  / 4);
    to_half<<<1024, 256>>>((const float4*)Wq, (uint2*)Wqh, D_  * D_  / 4);
    to_half<<<1024, 256>>>((const float4*)Wk, (uint2*)Wkh, KVD * D_  / 4);
    to_half<<<1024, 256>>>((const float4*)Wv, (uint2*)Wvh, KVD * D_  / 4);
    to_half<<<1024, 256>>>((const float4*)Wo, (uint2*)Woh, D_  * D_  / 4);

    // fused Q/K/V projections (fp16 in, half out)
    qkv_proj<<<dim3(32, 32), 256, GEMM_SMEM>>>(xh, Wqh, Wkh, Wvh, Qh, Kh, Vh);
    transpose_vh<<<dim3(32, 16, 2), 256>>>(Vh, Vth);

    // fused fp16 attention (scores + softmax + PV)
    flash_attn<<<dim3(16, 32), 256, FLASH_SMEM>>>(Qh, Kh, Vth, Oh);

    // output projection (fp16 MMA; final fp32 output)
    out_proj<<<dim3(16, 32), 256, GEMM_SMEM>>>(Oh, Woh, out);
}

// round 9
// speedup vs baseline: 2.1520x; 1.0784x over previous
#include <cuda_runtime.h>
#include <cuda_fp16.h>
#include <cstdint>
#include <math.h>

#define B_   2
#define T_   2048
#define D_   2048
#define NH   16
#define NKV  8
#define HD   128
#define KVD  1024
#define BT   4096

// ---------------- scratch (device globals; allocation-free) ----------------
__device__ __half g_xh [(size_t)BT  * D_ ];
__device__ __half g_Wqh[(size_t)D_  * D_ ];
__device__ __half g_Wkh[(size_t)KVD * D_ ];
__device__ __half g_Wvh[(size_t)KVD * D_ ];
__device__ __half g_Woh[(size_t)D_  * D_ ];
__device__ __half g_Qh [(size_t)BT  * D_ ];
__device__ __half g_Kh [(size_t)BT  * KVD];
__device__ __half g_Vh [(size_t)BT  * KVD];
__device__ __half g_Vth[(size_t)BT  * KVD];   // [b][d(1024)][t(2048)]
__device__ __half g_Oh [(size_t)BT  * D_ ];

// ---------------- helpers ----------------
__device__ __forceinline__ uint32_t smem_u32(const void* p) {
    uint32_t a;
    asm("{ .reg .u64 t; cvta.to.shared.u64 t, %1; cvt.u32.u64 %0, t; }" : "=r"(a) : "l"(p));
    return a;
}
__device__ __forceinline__ void cpa16(uint32_t dst, const void* src) {
    asm volatile("cp.async.cg.shared.global [%0], [%1], 16;" :: "r"(dst), "l"(src) : "memory");
}
__device__ __forceinline__ void mma_f16(float* c, const uint32_t* a, const uint32_t* b) {
    asm volatile("mma.sync.aligned.m16n8k16.row.col.f32.f16.f16.f32 "
        "{%0,%1,%2,%3}, {%4,%5,%6,%7}, {%8,%9}, {%0,%1,%2,%3};"
        : "+f"(c[0]), "+f"(c[1]), "+f"(c[2]), "+f"(c[3])
        : "r"(a[0]), "r"(a[1]), "r"(a[2]), "r"(a[3]), "r"(b[0]), "r"(b[1]));
}
__device__ __forceinline__ void ldm_x4(uint32_t* r, uint32_t addr) {
    asm volatile("ldmatrix.sync.aligned.m8n8.x4.shared.b16 {%0,%1,%2,%3}, [%4];"
        : "=r"(r[0]), "=r"(r[1]), "=r"(r[2]), "=r"(r[3]) : "r"(addr));
}

// ---------------------------------------------------------------------------
// fp16 MMA GEMM tile: C[128,128] = A @ B^T (half, K-contiguous), 4-stage,
// fragments via ldmatrix.x4.
// ---------------------------------------------------------------------------
#define HROW 40
#define HBUF (128 * HROW)
#define GEMM_SMEM (4 * 2 * HBUF * 2)       // 81920 bytes

template<bool HALF_OUT>
__device__ __forceinline__ void gemm_f16_body(
    const __half* __restrict__ A, int lda,
    const __half* __restrict__ B, int ldb,
    void* __restrict__ Cv, int ldc,
    int K, int m0, int n0)
{
    extern __shared__ __half hsm[];
    __half* As = hsm;
    __half* Bs = hsm + 4 * HBUF;

    const int tid  = threadIdx.x;
    const int lane = tid & 31;
    const int w    = tid >> 5;
    const int g    = lane >> 2;
    const int tg   = lane & 3;
    const int wm   = (w >> 2) << 6;
    const int wn   = (w & 3)  << 5;

    float acc[4][4][4];
    #pragma unroll
    for (int i = 0; i < 4; ++i)
        #pragma unroll
        for (int j = 0; j < 4; ++j)
            #pragma unroll
            for (int r = 0; r < 4; ++r)
                acc[i][j][r] = 0.0f;

    const __half* Ab = A + (size_t)m0 * lda;
    const __half* Bb = B + (size_t)n0 * ldb;
    const int nk = K >> 5;

    const int r0 = tid >> 2, s0 = (tid & 3) << 3;
    const int r1 = (tid + 256) >> 2;

    auto load_chunk = [&](int chunk) {
        const int st = chunk & 3;
        const int kt = chunk << 5;
        uint32_t aD = smem_u32(As + st * HBUF);
        uint32_t bD = smem_u32(Bs + st * HBUF);
        cpa16(aD + (r0 * HROW + s0) * 2, Ab + (size_t)r0 * lda + kt + s0);
        cpa16(bD + (r0 * HROW + s0) * 2, Bb + (size_t)r0 * ldb + kt + s0);
        cpa16(aD + (r1 * HROW + s0) * 2, Ab + (size_t)r1 * lda + kt + s0);
        cpa16(bD + (r1 * HROW + s0) * 2, Bb + (size_t)r1 * ldb + kt + s0);
        asm volatile("cp.async.commit_group;" ::: "memory");
    };

    load_chunk(0);
    if (nk > 1) load_chunk(1);
    if (nk > 2) load_chunk(2);

    // ldmatrix lane offsets (bytes)
    const uint32_t aSm = smem_u32(As);
    const uint32_t bSm = smem_u32(Bs);
    const uint32_t aLane = (uint32_t)(((wm + (lane & 15)) * HROW
                                       + ((lane >> 4) << 3)) * 2);
    const uint32_t bLane = (uint32_t)(((wn + (lane & 7) + ((lane >> 4) << 3)) * HROW
                                       + (((lane >> 3) & 1) << 3)) * 2);

    for (int i = 0; i < nk; ++i) {
        const int st = i & 3;
        const int rem = nk - 1 - i;
        if (rem >= 2)      asm volatile("cp.async.wait_group 2;" ::: "memory");
        else if (rem == 1) asm volatile("cp.async.wait_group 1;" ::: "memory");
        else               asm volatile("cp.async.wait_group 0;" ::: "memory");
        __syncthreads();
        if (i + 3 < nk) load_chunk(i + 3);

        const uint32_t aBase = aSm + (uint32_t)(st * HBUF * 2) + aLane;
        const uint32_t bBase = bSm + (uint32_t)(st * HBUF * 2) + bLane;
        #pragma unroll
        for (int ks = 0; ks < 2; ++ks) {
            const uint32_t kOff = (uint32_t)((ks << 4) * 2);
            uint32_t bf[2][4];
            ldm_x4(bf[0], bBase + kOff);
            ldm_x4(bf[1], bBase + kOff + 16 * HROW * 2);
            #pragma unroll
            for (int mt = 0; mt < 4; ++mt) {
                uint32_t af[4];
                ldm_x4(af, aBase + kOff + (uint32_t)(mt * 16 * HROW * 2));
                mma_f16(acc[mt][0], af, &bf[0][0]);
                mma_f16(acc[mt][1], af, &bf[0][2]);
                mma_f16(acc[mt][2], af, &bf[1][0]);
                mma_f16(acc[mt][3], af, &bf[1][2]);
            }
        }
    }

    #pragma unroll
    for (int mt = 0; mt < 4; ++mt) {
        const int rr = m0 + wm + (mt << 4) + g;
        #pragma unroll
        for (int nt = 0; nt < 4; ++nt) {
            const int cb = n0 + wn + (nt << 3) + (tg << 1);
            if (HALF_OUT) {
                __half* C = (__half*)Cv;
                *(__half2*)(C + (size_t)rr * ldc + cb) =
                    __floats2half2_rn(acc[mt][nt][0], acc[mt][nt][1]);
                *(__half2*)(C + (size_t)(rr + 8) * ldc + cb) =
                    __floats2half2_rn(acc[mt][nt][2], acc[mt][nt][3]);
            } else {
                float* C = (float*)Cv;
                *(float2*)(C + (size_t)rr * ldc + cb) =
                    make_float2(acc[mt][nt][0], acc[mt][nt][1]);
                *(float2*)(C + (size_t)(rr + 8) * ldc + cb) =
                    make_float2(acc[mt][nt][2], acc[mt][nt][3]);
            }
        }
    }
}

// fused QKV projection: bx 0..15 -> Q, 16..23 -> K, 24..31 -> V (half outputs)
__global__ void __launch_bounds__(256, 2)
qkv_proj(const __half* __restrict__ xh,
         const __half* __restrict__ Wq, const __half* __restrict__ Wk,
         const __half* __restrict__ Wv,
         __half* __restrict__ Q, __half* __restrict__ K, __half* __restrict__ V)
{
    const int bx = blockIdx.x;
    const __half* Bp;  __half* Cp;  int ldc, n0;
    if (bx < 16)      { Bp = Wq; Cp = Q; ldc = D_;  n0 = bx * 128; }
    else if (bx < 24) { Bp = Wk; Cp = K; ldc = KVD; n0 = (bx - 16) * 128; }
    else              { Bp = Wv; Cp = V; ldc = KVD; n0 = (bx - 24) * 128; }
    gemm_f16_body<true>(xh, D_, Bp, D_, Cp, ldc, D_, blockIdx.y * 128, n0);
}

__global__ void __launch_bounds__(256, 2)
out_proj(const __half* __restrict__ Oh, const __half* __restrict__ Wo,
         float* __restrict__ out)
{
    gemm_f16_body<false>(Oh, D_, Wo, D_, out, D_, D_,
                         blockIdx.y * 128, blockIdx.x * 128);
}

// half transpose: Vh[b][t][n] -> Vth[b][n][t], 64x64 tiles
__global__ void __launch_bounds__(256)
transpose_vh(const __half* __restrict__ V, __half* __restrict__ Vt)
{
    __shared__ __half tile[64][66];
    const int b  = blockIdx.z;
    const int t0 = blockIdx.x << 6, n0 = blockIdx.y << 6;
    const int tx = threadIdx.x & 31, ty = threadIdx.x >> 5;
    const __half* src = V  + (size_t)b * T_ * KVD;
    __half*       dst = Vt + (size_t)b * KVD * T_;
    #pragma unroll
    for (int j = 0; j < 8; ++j) {
        int r = ty + (j << 3);
        __half2 h = *(const __half2*)(src + (size_t)(t0 + r) * KVD + n0 + 2 * tx);
        tile[2 * tx][r]     = __low2half(h);
        tile[2 * tx + 1][r] = __high2half(h);
    }
    __syncthreads();
    #pragma unroll
    for (int j = 0; j < 8; ++j) {
        int r = ty + (j << 3);
        __half2 h = __halves2half2(tile[r][2 * tx], tile[r][2 * tx + 1]);
        *(__half2*)(dst + (size_t)(n0 + r) * T_ + t0 + 2 * tx) = h;
    }
}

// ---------------------------------------------------------------------------
// fp16 flash attention, fragments via ldmatrix.
// ---------------------------------------------------------------------------
#define SKH 136
#define SVH 72
#define SPH 72
#define SKB (64 * SKH)
#define SVB (128 * SVH)
#define FLASH_SMEM ((2*SKB + 2*SVB + 8*16*SPH) * 2)   // 90112 B

__global__ void __launch_bounds__(256, 1)
flash_attn(const __half* __restrict__ Qg, const __half* __restrict__ Kg,
           const __half* __restrict__ Vtg, __half* __restrict__ Og)
{
    extern __shared__ __half hsm[];
    __half* sK  = hsm;
    __half* sVt = hsm + 2 * SKB;
    __half* sP  = hsm + 2 * SKB + 2 * SVB;

    const int tid  = threadIdx.x;
    const int lane = tid & 31;
    const int w    = tid >> 5;
    const int g    = lane >> 2;
    const int tg   = lane & 3;
    const int z    = blockIdx.y, b = z >> 4, hq = z & 15, kv = hq >> 1;
    const int m0   = blockIdx.x << 7;
    const float inv_scale = 0.088388347648318447f;

    const size_t qbase  = (size_t)b * T_ * D_  + (size_t)hq * HD;
    const size_t kbase  = (size_t)b * T_ * KVD + (size_t)kv * HD;
    const size_t vtbase = ((size_t)b * KVD + (size_t)kv * HD) * T_;

    // ---- stage Q tile (128 x 128 halves) into sK region, stride SKH
    #pragma unroll
    for (int j = 0; j < 8; ++j) {
        int u = tid + (j << 8);
        int row = u >> 4, seg = (u & 15) << 3;
        cpa16(smem_u32(sK + row * SKH + seg),
              Qg + qbase + (size_t)(m0 + row) * D_ + seg);
    }
    asm volatile("cp.async.commit_group;" ::: "memory");
    asm volatile("cp.async.wait_group 0;" ::: "memory");
    __syncthreads();

    // Q fragments (scaled in fp32, rounded to half)
    uint32_t qf[8][4];
    {
        const __half* qr0 = sK + (w * 16 + g) * SKH;
        const __half* qr1 = qr0 + 8 * SKH;
        #pragma unroll
        for (int ks = 0; ks < 8; ++ks) {
            const int c = (ks << 4) + 2 * tg;
            #pragma unroll
            for (int h = 0; h < 2; ++h) {
                const int cc = c + h * 8;
                __half2 a0 = *(const __half2*)(qr0 + cc);
                __half2 a1 = *(const __half2*)(qr1 + cc);
                __half2 s0 = __floats2half2_rn(__low2float(a0) * inv_scale,
                                               __high2float(a0) * inv_scale);
                __half2 s1 = __floats2half2_rn(__low2float(a1) * inv_scale,
                                               __high2float(a1) * inv_scale);
                qf[ks][h * 2]     = *(uint32_t*)&s0;
                qf[ks][h * 2 + 1] = *(uint32_t*)&s1;
            }
        }
    }
    __syncthreads();

    float of[16][4];
    #pragma unroll
    for (int nt = 0; nt < 16; ++nt)
        #pragma unroll
        for (int r = 0; r < 4; ++r)
            of[nt][r] = 0.0f;
    float mprev0 = -1e30f, mprev1 = -1e30f, l0 = 0.0f, l1 = 0.0f;

    // stage kv iter 0: K 64x128, Vt 128x64
    #pragma unroll
    for (int j = 0; j < 4; ++j) {
        int u = tid + (j << 8);
        int kr = u >> 4, ks_ = (u & 15) << 3;
        cpa16(smem_u32(sK + kr * SKH + ks_), Kg + kbase + (size_t)kr * KVD + ks_);
        int vr = u >> 3, vs = (u & 7) << 3;
        cpa16(smem_u32(sVt + vr * SVH + vs), Vtg + vtbase + (size_t)vr * T_ + vs);
    }
    asm volatile("cp.async.commit_group;" ::: "memory");

    __half* Pw = sP + w * 16 * SPH;

    // ldmatrix lane offsets (bytes)
    const uint32_t sKsm = smem_u32(sK);
    const uint32_t sVsm = smem_u32(sVt);
    const uint32_t pWsm = smem_u32(Pw);
    const uint32_t kLane = (uint32_t)((((lane & 7) + ((lane >> 4) << 3)) * SKH
                                      + (((lane >> 3) & 1) << 3)) * 2);
    const uint32_t vLane = (uint32_t)((((lane & 7) + ((lane >> 4) << 3)) * SVH
                                      + (((lane >> 3) & 1) << 3)) * 2);
    const uint32_t pLane = (uint32_t)(((lane & 15) * SPH + ((lane >> 4) << 3)) * 2);

    for (int it = 0; it < 32; ++it) {
        const int buf = it & 1;
        if (it + 1 < 32) {
            const int nb = buf ^ 1;
            const int t0 = (it + 1) << 6;
            #pragma unroll
            for (int j = 0; j < 4; ++j) {
                int u = tid + (j << 8);
                int kr = u >> 4, ks_ = (u & 15) << 3;
                cpa16(smem_u32(sK + nb * SKB + kr * SKH + ks_),
                      Kg + kbase + (size_t)(t0 + kr) * KVD + ks_);
                int vr = u >> 3, vs = (u & 7) << 3;
                cpa16(smem_u32(sVt + nb * SVB + vr * SVH + vs),
                      Vtg + vtbase + (size_t)vr * T_ + t0 + vs);
            }
            asm volatile("cp.async.commit_group;" ::: "memory");
            asm volatile("cp.async.wait_group 1;" ::: "memory");
        } else {
            asm volatile("cp.async.wait_group 0;" ::: "memory");
        }
        __syncthreads();

        // S = Q @ K^T  (16 x 64 per warp, fp16 k16, K via ldmatrix)
        float sf[8][4];
        #pragma unroll
        for (int nt = 0; nt < 8; ++nt)
            sf[nt][0] = sf[nt][1] = sf[nt][2] = sf[nt][3] = 0.0f;
        {
            const uint32_t kBase = sKsm + (uint32_t)(buf * SKB * 2) + kLane;
            #pragma unroll
            for (int ks = 0; ks < 8; ++ks) {
                const uint32_t kOff = (uint32_t)((ks << 4) * 2);
                uint32_t bf[4][4];
                #pragma unroll
                for (int p = 0; p < 4; ++p)
                    ldm_x4(bf[p], kBase + kOff + (uint32_t)(p * 16 * SKH * 2));
                #pragma unroll
                for (int p = 0; p < 4; ++p) {
                    mma_f16(sf[2 * p],     qf[ks], &bf[p][0]);
                    mma_f16(sf[2 * p + 1], qf[ks], &bf[p][2]);
                }
            }
        }

        // online softmax
        float mx0 = mprev0, mx1 = mprev1;
        #pragma unroll
        for (int nt = 0; nt < 8; ++nt) {
            mx0 = fmaxf(mx0, fmaxf(sf[nt][0], sf[nt][1]));
            mx1 = fmaxf(mx1, fmaxf(sf[nt][2], sf[nt][3]));
        }
        mx0 = fmaxf(mx0, __shfl_xor_sync(0xffffffffu, mx0, 1));
        mx0 = fmaxf(mx0, __shfl_xor_sync(0xffffffffu, mx0, 2));
        mx1 = fmaxf(mx1, __shfl_xor_sync(0xffffffffu, mx1, 1));
        mx1 = fmaxf(mx1, __shfl_xor_sync(0xffffffffu, mx1, 2));

        const float sc0 = __expf(mprev0 - mx0);
        const float sc1 = __expf(mprev1 - mx1);
        mprev0 = mx0; mprev1 = mx1;

        float rs0 = 0.0f, rs1 = 0.0f;
        #pragma unroll
        for (int nt = 0; nt < 8; ++nt) {
            float p0 = __expf(sf[nt][0] - mx0);
            float p1 = __expf(sf[nt][1] - mx0);
            float p2 = __expf(sf[nt][2] - mx1);
            float p3 = __expf(sf[nt][3] - mx1);
            rs0 += p0 + p1;  rs1 += p2 + p3;
            *(__half2*)(Pw + g * SPH + nt * 8 + 2 * tg)       = __floats2half2_rn(p0, p1);
            *(__half2*)(Pw + (g + 8) * SPH + nt * 8 + 2 * tg) = __floats2half2_rn(p2, p3);
        }
        rs0 += __shfl_xor_sync(0xffffffffu, rs0, 1);
        rs0 += __shfl_xor_sync(0xffffffffu, rs0, 2);
        rs1 += __shfl_xor_sync(0xffffffffu, rs1, 1);
        rs1 += __shfl_xor_sync(0xffffffffu, rs1, 2);
        l0 = l0 * sc0 + rs0;
        l1 = l1 * sc1 + rs1;

        #pragma unroll
        for (int nt = 0; nt < 16; ++nt) {
            of[nt][0] *= sc0; of[nt][1] *= sc0;
            of[nt][2] *= sc1; of[nt][3] *= sc1;
        }
        __syncwarp();

        // O += P @ V  (16 x 128 per warp; P and Vt via ldmatrix)
        {
            const uint32_t pBase = pWsm + pLane;
            const uint32_t vBase = sVsm + (uint32_t)(buf * SVB * 2) + vLane;
            #pragma unroll
            for (int kc = 0; kc < 4; ++kc) {
                const uint32_t kOff = (uint32_t)((kc << 4) * 2);
                uint32_t aa[4];
                ldm_x4(aa, pBase + kOff);
                #pragma unroll
                for (int p = 0; p < 8; ++p) {
                    uint32_t bb[4];
                    ldm_x4(bb, vBase + kOff + (uint32_t)(p * 16 * SVH * 2));
                    mma_f16(of[2 * p],     aa, &bb[0]);
                    mma_f16(of[2 * p + 1], aa, &bb[2]);
                }
            }
        }
        __syncthreads();
    }

    // epilogue: O /= l, store half (input to fp16 out-proj)
    const float i0 = 1.0f / l0;
    const float i1 = 1.0f / l1;
    const int r0 = m0 + w * 16 + g;
    const size_t obase = (size_t)b * T_ * D_ + (size_t)hq * HD;
    #pragma unroll
    for (int nt = 0; nt < 16; ++nt) {
        const int c = nt * 8 + 2 * tg;
        *(__half2*)(Og + obase + (size_t)r0 * D_ + c) =
            __floats2half2_rn(of[nt][0] * i0, of[nt][1] * i0);
        *(__half2*)(Og + obase + (size_t)(r0 + 8) * D_ + c) =
            __floats2half2_rn(of[nt][2] * i1, of[nt][3] * i1);
    }
}

// convert fp32 -> fp16 (rn), vectorized
__global__ void __launch_bounds__(256)
to_half(const float4* __restrict__ in, uint2* __restrict__ out, int n4)
{
    int i = blockIdx.x * blockDim.x + threadIdx.x;
    int stride = gridDim.x * blockDim.x;
    for (; i < n4; i += stride) {
        float4 v = in[i];
        __half2 h0 = __floats2half2_rn(v.x, v.y);
        __half2 h1 = __floats2half2_rn(v.z, v.w);
        uint2 r;
        r.x = *(uint32_t*)&h0;
        r.y = *(uint32_t*)&h1;
        out[i] = r;
    }
}

// ---------------- host ----------------
extern "C" void kernel_launch(void* const* d_in, const int* in_sizes, int n_in,
                              void* d_out, int out_size)
{
    (void)in_sizes; (void)n_in; (void)out_size;
    const float* x  = (const float*)d_in[0];
    const float* Wq = (const float*)d_in[1];
    const float* Wk = (const float*)d_in[2];
    const float* Wv = (const float*)d_in[3];
    const float* Wo = (const float*)d_in[4];
    float* out = (float*)d_out;

    __half *xh, *Wqh, *Wkh, *Wvh, *Woh, *Qh, *Kh, *Vh, *Vth, *Oh;
    cudaGetSymbolAddress((void**)&xh,  g_xh);
    cudaGetSymbolAddress((void**)&Wqh, g_Wqh);
    cudaGetSymbolAddress((void**)&Wkh, g_Wkh);
    cudaGetSymbolAddress((void**)&Wvh, g_Wvh);
    cudaGetSymbolAddress((void**)&Woh, g_Woh);
    cudaGetSymbolAddress((void**)&Qh,  g_Qh);
    cudaGetSymbolAddress((void**)&Kh,  g_Kh);
    cudaGetSymbolAddress((void**)&Vh,  g_Vh);
    cudaGetSymbolAddress((void**)&Vth, g_Vth);
    cudaGetSymbolAddress((void**)&Oh,  g_Oh);

    cudaFuncSetAttribute(qkv_proj, cudaFuncAttributeMaxDynamicSharedMemorySize,
                         GEMM_SMEM);
    cudaFuncSetAttribute(out_proj, cudaFuncAttributeMaxDynamicSharedMemorySize,
                         GEMM_SMEM);
    cudaFuncSetAttribute(flash_attn, cudaFuncAttributeMaxDynamicSharedMemorySize,
                         FLASH_SMEM);

    // convert inputs to fp16 (rn)
    to_half<<<1024, 256>>>((const float4*)x,  (uint2*)xh,  BT  * D_  / 4);
    to_half<<<1024, 256>>>((const float4*)Wq, (uint2*)Wqh, D_  * D_  / 4);
    to_half<<<1024, 256>>>((const float4*)Wk, (uint2*)Wkh, KVD * D_  / 4);
    to_half<<<1024, 256>>>((const float4*)Wv, (uint2*)Wvh, KVD * D_  / 4);
    to_half<<<1024, 256>>>((const float4*)Wo, (uint2*)Woh, D_  * D_  / 4);

    // fused Q/K/V projections (fp16 in, half out)
    qkv_proj<<<dim3(32, 32), 256, GEMM_SMEM>>>(xh, Wqh, Wkh, Wvh, Qh, Kh, Vh);
    transpose_vh<<<dim3(32, 16, 2), 256>>>(Vh, Vth);

    // fused fp16 attention (scores + softmax + PV)
    flash_attn<<<dim3(16, 32), 256, FLASH_SMEM>>>(Qh, Kh, Vth, Oh);

    // output projection (fp16 MMA; final fp32 output)
    out_proj<<<dim3(16, 32), 256, GEMM_SMEM>>>(Oh, Woh, out);
}

// round 10
// speedup vs baseline: 2.2249x; 1.0339x over previous
#include <cuda_runtime.h>
#include <cuda_fp16.h>
#include <cstdint>
#include <math.h>

#define B_   2
#define T_   2048
#define D_   2048
#define NH   16
#define NKV  8
#define HD   128
#define KVD  1024
#define BT   4096

// ---------------- scratch (device globals; allocation-free) ----------------
__device__ __half g_xh [(size_t)BT  * D_ ];
__device__ __half g_Wqh[(size_t)D_  * D_ ];
__device__ __half g_Wkh[(size_t)KVD * D_ ];
__device__ __half g_Wvh[(size_t)KVD * D_ ];
__device__ __half g_Woh[(size_t)D_  * D_ ];
__device__ __half g_Qh [(size_t)BT  * D_ ];
__device__ __half g_Kh [(size_t)BT  * KVD];
__device__ __half g_Vh [(size_t)BT  * KVD];
__device__ __half g_Vth[(size_t)BT  * KVD];   // [b][d(1024)][t(2048)]
__device__ __half g_Oh [(size_t)BT  * D_ ];

// ---------------- helpers ----------------
__device__ __forceinline__ uint32_t smem_u32(const void* p) {
    uint32_t a;
    asm("{ .reg .u64 t; cvta.to.shared.u64 t, %1; cvt.u32.u64 %0, t; }" : "=r"(a) : "l"(p));
    return a;
}
__device__ __forceinline__ void cpa16(uint32_t dst, const void* src) {
    asm volatile("cp.async.cg.shared.global [%0], [%1], 16;" :: "r"(dst), "l"(src) : "memory");
}
__device__ __forceinline__ void mma_f16(float* c, const uint32_t* a, const uint32_t* b) {
    asm volatile("mma.sync.aligned.m16n8k16.row.col.f32.f16.f16.f32 "
        "{%0,%1,%2,%3}, {%4,%5,%6,%7}, {%8,%9}, {%0,%1,%2,%3};"
        : "+f"(c[0]), "+f"(c[1]), "+f"(c[2]), "+f"(c[3])
        : "r"(a[0]), "r"(a[1]), "r"(a[2]), "r"(a[3]), "r"(b[0]), "r"(b[1]));
}
__device__ __forceinline__ void ldm_x4(uint32_t* r, uint32_t addr) {
    asm volatile("ldmatrix.sync.aligned.m8n8.x4.shared.b16 {%0,%1,%2,%3}, [%4];"
        : "=r"(r[0]), "=r"(r[1]), "=r"(r[2]), "=r"(r[3]) : "r"(addr));
}

// ---------------------------------------------------------------------------
// fp16 MMA GEMM tile: C[128,128] = A @ B^T (half, K-contiguous), 4-stage,
// fragments via ldmatrix.x4.  (unchanged from R9 — proven)
// ---------------------------------------------------------------------------
#define HROW 40
#define HBUF (128 * HROW)
#define GEMM_SMEM (4 * 2 * HBUF * 2)       // 81920 bytes

template<bool HALF_OUT>
__device__ __forceinline__ void gemm_f16_body(
    const __half* __restrict__ A, int lda,
    const __half* __restrict__ B, int ldb,
    void* __restrict__ Cv, int ldc,
    int K, int m0, int n0)
{
    extern __shared__ __half hsm[];
    __half* As = hsm;
    __half* Bs = hsm + 4 * HBUF;

    const int tid  = threadIdx.x;
    const int lane = tid & 31;
    const int w    = tid >> 5;
    const int g    = lane >> 2;
    const int tg   = lane & 3;
    const int wm   = (w >> 2) << 6;
    const int wn   = (w & 3)  << 5;

    float acc[4][4][4];
    #pragma unroll
    for (int i = 0; i < 4; ++i)
        #pragma unroll
        for (int j = 0; j < 4; ++j)
            #pragma unroll
            for (int r = 0; r < 4; ++r)
                acc[i][j][r] = 0.0f;

    const __half* Ab = A + (size_t)m0 * lda;
    const __half* Bb = B + (size_t)n0 * ldb;
    const int nk = K >> 5;

    const int r0 = tid >> 2, s0 = (tid & 3) << 3;
    const int r1 = (tid + 256) >> 2;

    auto load_chunk = [&](int chunk) {
        const int st = chunk & 3;
        const int kt = chunk << 5;
        uint32_t aD = smem_u32(As + st * HBUF);
        uint32_t bD = smem_u32(Bs + st * HBUF);
        cpa16(aD + (r0 * HROW + s0) * 2, Ab + (size_t)r0 * lda + kt + s0);
        cpa16(bD + (r0 * HROW + s0) * 2, Bb + (size_t)r0 * ldb + kt + s0);
        cpa16(aD + (r1 * HROW + s0) * 2, Ab + (size_t)r1 * lda + kt + s0);
        cpa16(bD + (r1 * HROW + s0) * 2, Bb + (size_t)r1 * ldb + kt + s0);
        asm volatile("cp.async.commit_group;" ::: "memory");
    };

    load_chunk(0);
    if (nk > 1) load_chunk(1);
    if (nk > 2) load_chunk(2);

    const uint32_t aSm = smem_u32(As);
    const uint32_t bSm = smem_u32(Bs);
    const uint32_t aLane = (uint32_t)(((wm + (lane & 15)) * HROW
                                       + ((lane >> 4) << 3)) * 2);
    const uint32_t bLane = (uint32_t)(((wn + (lane & 7) + ((lane >> 4) << 3)) * HROW
                                       + (((lane >> 3) & 1) << 3)) * 2);

    for (int i = 0; i < nk; ++i) {
        const int st = i & 3;
        const int rem = nk - 1 - i;
        if (rem >= 2)      asm volatile("cp.async.wait_group 2;" ::: "memory");
        else if (rem == 1) asm volatile("cp.async.wait_group 1;" ::: "memory");
        else               asm volatile("cp.async.wait_group 0;" ::: "memory");
        __syncthreads();
        if (i + 3 < nk) load_chunk(i + 3);

        const uint32_t aBase = aSm + (uint32_t)(st * HBUF * 2) + aLane;
        const uint32_t bBase = bSm + (uint32_t)(st * HBUF * 2) + bLane;
        #pragma unroll
        for (int ks = 0; ks < 2; ++ks) {
            const uint32_t kOff = (uint32_t)((ks << 4) * 2);
            uint32_t bf[2][4];
            ldm_x4(bf[0], bBase + kOff);
            ldm_x4(bf[1], bBase + kOff + 16 * HROW * 2);
            #pragma unroll
            for (int mt = 0; mt < 4; ++mt) {
                uint32_t af[4];
                ldm_x4(af, aBase + kOff + (uint32_t)(mt * 16 * HROW * 2));
                mma_f16(acc[mt][0], af, &bf[0][0]);
                mma_f16(acc[mt][1], af, &bf[0][2]);
                mma_f16(acc[mt][2], af, &bf[1][0]);
                mma_f16(acc[mt][3], af, &bf[1][2]);
            }
        }
    }

    #pragma unroll
    for (int mt = 0; mt < 4; ++mt) {
        const int rr = m0 + wm + (mt << 4) + g;
        #pragma unroll
        for (int nt = 0; nt < 4; ++nt) {
            const int cb = n0 + wn + (nt << 3) + (tg << 1);
            if (HALF_OUT) {
                __half* C = (__half*)Cv;
                *(__half2*)(C + (size_t)rr * ldc + cb) =
                    __floats2half2_rn(acc[mt][nt][0], acc[mt][nt][1]);
                *(__half2*)(C + (size_t)(rr + 8) * ldc + cb) =
                    __floats2half2_rn(acc[mt][nt][2], acc[mt][nt][3]);
            } else {
                float* C = (float*)Cv;
                *(float2*)(C + (size_t)rr * ldc + cb) =
                    make_float2(acc[mt][nt][0], acc[mt][nt][1]);
                *(float2*)(C + (size_t)(rr + 8) * ldc + cb) =
                    make_float2(acc[mt][nt][2], acc[mt][nt][3]);
            }
        }
    }
}

// fused QKV projection: bx 0..15 -> Q, 16..23 -> K, 24..31 -> V (half outputs)
__global__ void __launch_bounds__(256, 2)
qkv_proj(const __half* __restrict__ xh,
         const __half* __restrict__ Wq, const __half* __restrict__ Wk,
         const __half* __restrict__ Wv,
         __half* __restrict__ Q, __half* __restrict__ K, __half* __restrict__ V)
{
    const int bx = blockIdx.x;
    const __half* Bp;  __half* Cp;  int ldc, n0;
    if (bx < 16)      { Bp = Wq; Cp = Q; ldc = D_;  n0 = bx * 128; }
    else if (bx < 24) { Bp = Wk; Cp = K; ldc = KVD; n0 = (bx - 16) * 128; }
    else              { Bp = Wv; Cp = V; ldc = KVD; n0 = (bx - 24) * 128; }
    gemm_f16_body<true>(xh, D_, Bp, D_, Cp, ldc, D_, blockIdx.y * 128, n0);
}

__global__ void __launch_bounds__(256, 2)
out_proj(const __half* __restrict__ Oh, const __half* __restrict__ Wo,
         float* __restrict__ out)
{
    gemm_f16_body<false>(Oh, D_, Wo, D_, out, D_, D_,
                         blockIdx.y * 128, blockIdx.x * 128);
}

// half transpose: Vh[b][t][n] -> Vth[b][n][t], 64x64 tiles
__global__ void __launch_bounds__(256)
transpose_vh(const __half* __restrict__ V, __half* __restrict__ Vt)
{
    __shared__ __half tile[64][66];
    const int b  = blockIdx.z;
    const int t0 = blockIdx.x << 6, n0 = blockIdx.y << 6;
    const int tx = threadIdx.x & 31, ty = threadIdx.x >> 5;
    const __half* src = V  + (size_t)b * T_ * KVD;
    __half*       dst = Vt + (size_t)b * KVD * T_;
    #pragma unroll
    for (int j = 0; j < 8; ++j) {
        int r = ty + (j << 3);
        __half2 h = *(const __half2*)(src + (size_t)(t0 + r) * KVD + n0 + 2 * tx);
        tile[2 * tx][r]     = __low2half(h);
        tile[2 * tx + 1][r] = __high2half(h);
    }
    __syncthreads();
    #pragma unroll
    for (int j = 0; j < 8; ++j) {
        int r = ty + (j << 3);
        __half2 h = __halves2half2(tile[r][2 * tx], tile[r][2 * tx + 1]);
        *(__half2*)(dst + (size_t)(n0 + r) * T_ + t0 + 2 * tx) = h;
    }
}

// ---------------------------------------------------------------------------
// fp16 flash attention, KV tile 128, fragments via ldmatrix.
// smem (halves): sK[2][128][136], sVt[2][128][136], sP[8][16][136].
// ---------------------------------------------------------------------------
#define SKH 136
#define SVH 136
#define SPH 136
#define SKB (128 * SKH)
#define SVB (128 * SVH)
#define FLASH_SMEM ((2*SKB + 2*SVB + 8*16*SPH) * 2)   // 174080 B

__global__ void __launch_bounds__(256, 1)
flash_attn(const __half* __restrict__ Qg, const __half* __restrict__ Kg,
           const __half* __restrict__ Vtg, __half* __restrict__ Og)
{
    extern __shared__ __half hsm[];
    __half* sK  = hsm;
    __half* sVt = hsm + 2 * SKB;
    __half* sP  = hsm + 2 * SKB + 2 * SVB;

    const int tid  = threadIdx.x;
    const int lane = tid & 31;
    const int w    = tid >> 5;
    const int g    = lane >> 2;
    const int tg   = lane & 3;
    const int z    = blockIdx.y, b = z >> 4, hq = z & 15, kv = hq >> 1;
    const int m0   = blockIdx.x << 7;
    const float inv_scale = 0.088388347648318447f;

    const size_t qbase  = (size_t)b * T_ * D_  + (size_t)hq * HD;
    const size_t kbase  = (size_t)b * T_ * KVD + (size_t)kv * HD;
    const size_t vtbase = ((size_t)b * KVD + (size_t)kv * HD) * T_;

    // ---- stage Q tile (128 x 128 halves) into sK region, stride SKH
    #pragma unroll
    for (int j = 0; j < 8; ++j) {
        int u = tid + (j << 8);
        int row = u >> 4, seg = (u & 15) << 3;
        cpa16(smem_u32(sK + row * SKH + seg),
              Qg + qbase + (size_t)(m0 + row) * D_ + seg);
    }
    asm volatile("cp.async.commit_group;" ::: "memory");
    asm volatile("cp.async.wait_group 0;" ::: "memory");
    __syncthreads();

    // Q fragments (scaled in fp32, rounded to half)
    uint32_t qf[8][4];
    {
        const __half* qr0 = sK + (w * 16 + g) * SKH;
        const __half* qr1 = qr0 + 8 * SKH;
        #pragma unroll
        for (int ks = 0; ks < 8; ++ks) {
            const int c = (ks << 4) + 2 * tg;
            #pragma unroll
            for (int h = 0; h < 2; ++h) {
                const int cc = c + h * 8;
                __half2 a0 = *(const __half2*)(qr0 + cc);
                __half2 a1 = *(const __half2*)(qr1 + cc);
                __half2 s0 = __floats2half2_rn(__low2float(a0) * inv_scale,
                                               __high2float(a0) * inv_scale);
                __half2 s1 = __floats2half2_rn(__low2float(a1) * inv_scale,
                                               __high2float(a1) * inv_scale);
                qf[ks][h * 2]     = *(uint32_t*)&s0;
                qf[ks][h * 2 + 1] = *(uint32_t*)&s1;
            }
        }
    }
    __syncthreads();

    float of[16][4];
    #pragma unroll
    for (int nt = 0; nt < 16; ++nt)
        #pragma unroll
        for (int r = 0; r < 4; ++r)
            of[nt][r] = 0.0f;
    float mprev0 = -1e30f, mprev1 = -1e30f, l0 = 0.0f, l1 = 0.0f;

    // stage kv iter 0: K 128x128, Vt 128x128
    #pragma unroll
    for (int j = 0; j < 8; ++j) {
        int u = tid + (j << 8);
        int r = u >> 4, s = (u & 15) << 3;
        cpa16(smem_u32(sK  + r * SKH + s), Kg  + kbase  + (size_t)r * KVD + s);
        cpa16(smem_u32(sVt + r * SVH + s), Vtg + vtbase + (size_t)r * T_  + s);
    }
    asm volatile("cp.async.commit_group;" ::: "memory");

    __half* Pw = sP + w * 16 * SPH;

    // ldmatrix lane offsets (bytes)
    const uint32_t sKsm = smem_u32(sK);
    const uint32_t sVsm = smem_u32(sVt);
    const uint32_t pWsm = smem_u32(Pw);
    const uint32_t kLane = (uint32_t)((((lane & 7) + ((lane >> 4) << 3)) * SKH
                                      + (((lane >> 3) & 1) << 3)) * 2);
    const uint32_t vLane = (uint32_t)((((lane & 7) + ((lane >> 4) << 3)) * SVH
                                      + (((lane >> 3) & 1) << 3)) * 2);
    const uint32_t pLane = (uint32_t)(((lane & 15) * SPH + ((lane >> 4) << 3)) * 2);

    for (int it = 0; it < 16; ++it) {
        const int buf = it & 1;
        if (it + 1 < 16) {
            const int nb = buf ^ 1;
            const int t0 = (it + 1) << 7;
            #pragma unroll
            for (int j = 0; j < 8; ++j) {
                int u = tid + (j << 8);
                int r = u >> 4, s = (u & 15) << 3;
                cpa16(smem_u32(sK + nb * SKB + r * SKH + s),
                      Kg + kbase + (size_t)(t0 + r) * KVD + s);
                cpa16(smem_u32(sVt + nb * SVB + r * SVH + s),
                      Vtg + vtbase + (size_t)r * T_ + t0 + s);
            }
            asm volatile("cp.async.commit_group;" ::: "memory");
            asm volatile("cp.async.wait_group 1;" ::: "memory");
        } else {
            asm volatile("cp.async.wait_group 0;" ::: "memory");
        }
        __syncthreads();

        // S = Q @ K^T  (16 x 128 per warp, K via ldmatrix)
        float sf[16][4];
        #pragma unroll
        for (int nt = 0; nt < 16; ++nt)
            sf[nt][0] = sf[nt][1] = sf[nt][2] = sf[nt][3] = 0.0f;
        {
            const uint32_t kBase = sKsm + (uint32_t)(buf * SKB * 2) + kLane;
            #pragma unroll
            for (int ks = 0; ks < 8; ++ks) {
                const uint32_t kOff = (uint32_t)((ks << 4) * 2);
                #pragma unroll
                for (int p = 0; p < 8; ++p) {
                    uint32_t bf[4];
                    ldm_x4(bf, kBase + kOff + (uint32_t)(p * 16 * SKH * 2));
                    mma_f16(sf[2 * p],     qf[ks], &bf[0]);
                    mma_f16(sf[2 * p + 1], qf[ks], &bf[2]);
                }
            }
        }

        // online softmax
        float mx0 = mprev0, mx1 = mprev1;
        #pragma unroll
        for (int nt = 0; nt < 16; ++nt) {
            mx0 = fmaxf(mx0, fmaxf(sf[nt][0], sf[nt][1]));
            mx1 = fmaxf(mx1, fmaxf(sf[nt][2], sf[nt][3]));
        }
        mx0 = fmaxf(mx0, __shfl_xor_sync(0xffffffffu, mx0, 1));
        mx0 = fmaxf(mx0, __shfl_xor_sync(0xffffffffu, mx0, 2));
        mx1 = fmaxf(mx1, __shfl_xor_sync(0xffffffffu, mx1, 1));
        mx1 = fmaxf(mx1, __shfl_xor_sync(0xffffffffu, mx1, 2));

        const float sc0 = __expf(mprev0 - mx0);
        const float sc1 = __expf(mprev1 - mx1);
        mprev0 = mx0; mprev1 = mx1;

        float rs0 = 0.0f, rs1 = 0.0f;
        #pragma unroll
        for (int nt = 0; nt < 16; ++nt) {
            float p0 = __expf(sf[nt][0] - mx0);
            float p1 = __expf(sf[nt][1] - mx0);
            float p2 = __expf(sf[nt][2] - mx1);
            float p3 = __expf(sf[nt][3] - mx1);
            rs0 += p0 + p1;  rs1 += p2 + p3;
            *(__half2*)(Pw + g * SPH + nt * 8 + 2 * tg)       = __floats2half2_rn(p0, p1);
            *(__half2*)(Pw + (g + 8) * SPH + nt * 8 + 2 * tg) = __floats2half2_rn(p2, p3);
        }
        rs0 += __shfl_xor_sync(0xffffffffu, rs0, 1);
        rs0 += __shfl_xor_sync(0xffffffffu, rs0, 2);
        rs1 += __shfl_xor_sync(0xffffffffu, rs1, 1);
        rs1 += __shfl_xor_sync(0xffffffffu, rs1, 2);
        l0 = l0 * sc0 + rs0;
        l1 = l1 * sc1 + rs1;

        #pragma unroll
        for (int nt = 0; nt < 16; ++nt) {
            of[nt][0] *= sc0; of[nt][1] *= sc0;
            of[nt][2] *= sc1; of[nt][3] *= sc1;
        }
        __syncwarp();

        // O += P @ V  (16 x 128 per warp; P and Vt via ldmatrix)
        {
            const uint32_t pBase = pWsm + pLane;
            const uint32_t vBase = sVsm + (uint32_t)(buf * SVB * 2) + vLane;
            #pragma unroll
            for (int kc = 0; kc < 8; ++kc) {
                const uint32_t kOff = (uint32_t)((kc << 4) * 2);
                uint32_t aa[4];
                ldm_x4(aa, pBase + kOff);
                #pragma unroll
                for (int p = 0; p < 8; ++p) {
                    uint32_t bb[4];
                    ldm_x4(bb, vBase + kOff + (uint32_t)(p * 16 * SVH * 2));
                    mma_f16(of[2 * p],     aa, &bb[0]);
                    mma_f16(of[2 * p + 1], aa, &bb[2]);
                }
            }
        }
        __syncthreads();
    }

    // epilogue: O /= l, store half (input to fp16 out-proj)
    const float i0 = 1.0f / l0;
    const float i1 = 1.0f / l1;
    const int r0 = m0 + w * 16 + g;
    const size_t obase = (size_t)b * T_ * D_ + (size_t)hq * HD;
    #pragma unroll
    for (int nt = 0; nt < 16; ++nt) {
        const int c = nt * 8 + 2 * tg;
        *(__half2*)(Og + obase + (size_t)r0 * D_ + c) =
            __floats2half2_rn(of[nt][0] * i0, of[nt][1] * i0);
        *(__half2*)(Og + obase + (size_t)(r0 + 8) * D_ + c) =
            __floats2half2_rn(of[nt][2] * i1, of[nt][3] * i1);
    }
}

// fused conversion: all five fp32 tensors -> fp16 in one launch
#define N4_X  (BT  * D_ / 4)
#define N4_WQ (D_  * D_ / 4)
#define N4_WK (KVD * D_ / 4)
#define N4_WV (KVD * D_ / 4)
#define N4_WO (D_  * D_ / 4)
#define N4_TOT (N4_X + N4_WQ + N4_WK + N4_WV + N4_WO)

__global__ void __launch_bounds__(256)
to_half_all(const float4* __restrict__ x,  uint2* __restrict__ xh,
            const float4* __restrict__ wq, uint2* __restrict__ wqh,
            const float4* __restrict__ wk, uint2* __restrict__ wkh,
            const float4* __restrict__ wv, uint2* __restrict__ wvh,
            const float4* __restrict__ wo, uint2* __restrict__ woh)
{
    int i = blockIdx.x * blockDim.x + threadIdx.x;
    const int stride = gridDim.x * blockDim.x;
    for (; i < N4_TOT; i += stride) {
        const float4* src;  uint2* dst;  int off = i;
        if (off < N4_X)                        { src = x;  dst = xh; }
        else if ((off -= N4_X)  < N4_WQ)       { src = wq; dst = wqh; }
        else if ((off -= N4_WQ) < N4_WK)       { src = wk; dst = wkh; }
        else if ((off -= N4_WK) < N4_WV)       { src = wv; dst = wvh; }
        else { off -= N4_WV;                     src = wo; dst = woh; }
        float4 v = src[off];
        __half2 h0 = __floats2half2_rn(v.x, v.y);
        __half2 h1 = __floats2half2_rn(v.z, v.w);
        uint2 r;
        r.x = *(uint32_t*)&h0;
        r.y = *(uint32_t*)&h1;
        dst[off] = r;
    }
}

// ---------------- host ----------------
extern "C" void kernel_launch(void* const* d_in, const int* in_sizes, int n_in,
                              void* d_out, int out_size)
{
    (void)in_sizes; (void)n_in; (void)out_size;
    const float* x  = (const float*)d_in[0];
    const float* Wq = (const float*)d_in[1];
    const float* Wk = (const float*)d_in[2];
    const float* Wv = (const float*)d_in[3];
    const float* Wo = (const float*)d_in[4];
    float* out = (float*)d_out;

    __half *xh, *Wqh, *Wkh, *Wvh, *Woh, *Qh, *Kh, *Vh, *Vth, *Oh;
    cudaGetSymbolAddress((void**)&xh,  g_xh);
    cudaGetSymbolAddress((void**)&Wqh, g_Wqh);
    cudaGetSymbolAddress((void**)&Wkh, g_Wkh);
    cudaGetSymbolAddress((void**)&Wvh, g_Wvh);
    cudaGetSymbolAddress((void**)&Woh, g_Woh);
    cudaGetSymbolAddress((void**)&Qh,  g_Qh);
    cudaGetSymbolAddress((void**)&Kh,  g_Kh);
    cudaGetSymbolAddress((void**)&Vh,  g_Vh);
    cudaGetSymbolAddress((void**)&Vth, g_Vth);
    cudaGetSymbolAddress((void**)&Oh,  g_Oh);

    cudaFuncSetAttribute(qkv_proj, cudaFuncAttributeMaxDynamicSharedMemorySize,
                         GEMM_SMEM);
    cudaFuncSetAttribute(out_proj, cudaFuncAttributeMaxDynamicSharedMemorySize,
                         GEMM_SMEM);
    cudaFuncSetAttribute(flash_attn, cudaFuncAttributeMaxDynamicSharedMemorySize,
                         FLASH_SMEM);

    // fused conversion (one launch)
    to_half_all<<<2048, 256>>>((const float4*)x,  (uint2*)xh,
                               (const float4*)Wq, (uint2*)Wqh,
                               (const float4*)Wk, (uint2*)Wkh,
                               (const float4*)Wv, (uint2*)Wvh,
                               (const float4*)Wo, (uint2*)Woh);

    // fused Q/K/V projections (fp16 in, half out)
    qkv_proj<<<dim3(32, 32), 256, GEMM_SMEM>>>(xh, Wqh, Wkh, Wvh, Qh, Kh, Vh);
    transpose_vh<<<dim3(32, 16, 2), 256>>>(Vh, Vth);

    // fused fp16 attention (scores + softmax + PV), KV tile 128
    flash_attn<<<dim3(16, 32), 256, FLASH_SMEM>>>(Qh, Kh, Vth, Oh);

    // output projection (fp16 MMA; final fp32 output)
    out_proj<<<dim3(16, 32), 256, GEMM_SMEM>>>(Oh, Woh, out);
}

// round 11
// speedup vs baseline: 2.2902x; 1.0293x over previous
#include <cuda_runtime.h>
#include <cuda_fp16.h>
#include <cstdint>
#include <math.h>

#define B_   2
#define T_   2048
#define D_   2048
#define NH   16
#define NKV  8
#define HD   128
#define KVD  1024
#define BT   4096

// ---------------- scratch (device globals; allocation-free) ----------------
__device__ __half g_xh [(size_t)BT  * D_ ];
__device__ __half g_Wqh[(size_t)D_  * D_ ];
__device__ __half g_Wkh[(size_t)KVD * D_ ];
__device__ __half g_Wvh[(size_t)KVD * D_ ];
__device__ __half g_Woh[(size_t)D_  * D_ ];
__device__ __half g_Qh [(size_t)BT  * D_ ];
__device__ __half g_Kh [(size_t)BT  * KVD];
__device__ __half g_Vh [(size_t)BT  * KVD];
__device__ __half g_Vth[(size_t)BT  * KVD];   // [b][d(1024)][t(2048)]
__device__ __half g_Oh [(size_t)BT  * D_ ];

// ---------------- helpers ----------------
__device__ __forceinline__ uint32_t smem_u32(const void* p) {
    uint32_t a;
    asm("{ .reg .u64 t; cvta.to.shared.u64 t, %1; cvt.u32.u64 %0, t; }" : "=r"(a) : "l"(p));
    return a;
}
__device__ __forceinline__ void cpa16(uint32_t dst, const void* src) {
    asm volatile("cp.async.cg.shared.global [%0], [%1], 16;" :: "r"(dst), "l"(src) : "memory");
}
__device__ __forceinline__ void mma_f16(float* c, const uint32_t* a, const uint32_t* b) {
    asm volatile("mma.sync.aligned.m16n8k16.row.col.f32.f16.f16.f32 "
        "{%0,%1,%2,%3}, {%4,%5,%6,%7}, {%8,%9}, {%0,%1,%2,%3};"
        : "+f"(c[0]), "+f"(c[1]), "+f"(c[2]), "+f"(c[3])
        : "r"(a[0]), "r"(a[1]), "r"(a[2]), "r"(a[3]), "r"(b[0]), "r"(b[1]));
}
__device__ __forceinline__ void ldm_x4(uint32_t* r, uint32_t addr) {
    asm volatile("ldmatrix.sync.aligned.m8n8.x4.shared.b16 {%0,%1,%2,%3}, [%4];"
        : "=r"(r[0]), "=r"(r[1]), "=r"(r[2]), "=r"(r[3]) : "r"(addr));
}

// ---------------------------------------------------------------------------
// fp16 MMA GEMM tile: C[128,128] = A @ B^T (half, K-contiguous), 4-stage,
// fragments via ldmatrix.x4.  (unchanged — proven)
// ---------------------------------------------------------------------------
#define HROW 40
#define HBUF (128 * HROW)
#define GEMM_SMEM (4 * 2 * HBUF * 2)       // 81920 bytes

template<bool HALF_OUT>
__device__ __forceinline__ void gemm_f16_body(
    const __half* __restrict__ A, int lda,
    const __half* __restrict__ B, int ldb,
    void* __restrict__ Cv, int ldc,
    int K, int m0, int n0)
{
    extern __shared__ __half hsm[];
    __half* As = hsm;
    __half* Bs = hsm + 4 * HBUF;

    const int tid  = threadIdx.x;
    const int lane = tid & 31;
    const int w    = tid >> 5;
    const int g    = lane >> 2;
    const int tg   = lane & 3;
    const int wm   = (w >> 2) << 6;
    const int wn   = (w & 3)  << 5;

    float acc[4][4][4];
    #pragma unroll
    for (int i = 0; i < 4; ++i)
        #pragma unroll
        for (int j = 0; j < 4; ++j)
            #pragma unroll
            for (int r = 0; r < 4; ++r)
                acc[i][j][r] = 0.0f;

    const __half* Ab = A + (size_t)m0 * lda;
    const __half* Bb = B + (size_t)n0 * ldb;
    const int nk = K >> 5;

    const int r0 = tid >> 2, s0 = (tid & 3) << 3;
    const int r1 = (tid + 256) >> 2;

    auto load_chunk = [&](int chunk) {
        const int st = chunk & 3;
        const int kt = chunk << 5;
        uint32_t aD = smem_u32(As + st * HBUF);
        uint32_t bD = smem_u32(Bs + st * HBUF);
        cpa16(aD + (r0 * HROW + s0) * 2, Ab + (size_t)r0 * lda + kt + s0);
        cpa16(bD + (r0 * HROW + s0) * 2, Bb + (size_t)r0 * ldb + kt + s0);
        cpa16(aD + (r1 * HROW + s0) * 2, Ab + (size_t)r1 * lda + kt + s0);
        cpa16(bD + (r1 * HROW + s0) * 2, Bb + (size_t)r1 * ldb + kt + s0);
        asm volatile("cp.async.commit_group;" ::: "memory");
    };

    load_chunk(0);
    if (nk > 1) load_chunk(1);
    if (nk > 2) load_chunk(2);

    const uint32_t aSm = smem_u32(As);
    const uint32_t bSm = smem_u32(Bs);
    const uint32_t aLane = (uint32_t)(((wm + (lane & 15)) * HROW
                                       + ((lane >> 4) << 3)) * 2);
    const uint32_t bLane = (uint32_t)(((wn + (lane & 7) + ((lane >> 4) << 3)) * HROW
                                       + (((lane >> 3) & 1) << 3)) * 2);

    for (int i = 0; i < nk; ++i) {
        const int st = i & 3;
        const int rem = nk - 1 - i;
        if (rem >= 2)      asm volatile("cp.async.wait_group 2;" ::: "memory");
        else if (rem == 1) asm volatile("cp.async.wait_group 1;" ::: "memory");
        else               asm volatile("cp.async.wait_group 0;" ::: "memory");
        __syncthreads();
        if (i + 3 < nk) load_chunk(i + 3);

        const uint32_t aBase = aSm + (uint32_t)(st * HBUF * 2) + aLane;
        const uint32_t bBase = bSm + (uint32_t)(st * HBUF * 2) + bLane;
        #pragma unroll
        for (int ks = 0; ks < 2; ++ks) {
            const uint32_t kOff = (uint32_t)((ks << 4) * 2);
            uint32_t bf[2][4];
            ldm_x4(bf[0], bBase + kOff);
            ldm_x4(bf[1], bBase + kOff + 16 * HROW * 2);
            #pragma unroll
            for (int mt = 0; mt < 4; ++mt) {
                uint32_t af[4];
                ldm_x4(af, aBase + kOff + (uint32_t)(mt * 16 * HROW * 2));
                mma_f16(acc[mt][0], af, &bf[0][0]);
                mma_f16(acc[mt][1], af, &bf[0][2]);
                mma_f16(acc[mt][2], af, &bf[1][0]);
                mma_f16(acc[mt][3], af, &bf[1][2]);
            }
        }
    }

    #pragma unroll
    for (int mt = 0; mt < 4; ++mt) {
        const int rr = m0 + wm + (mt << 4) + g;
        #pragma unroll
        for (int nt = 0; nt < 4; ++nt) {
            const int cb = n0 + wn + (nt << 3) + (tg << 1);
            if (HALF_OUT) {
                __half* C = (__half*)Cv;
                *(__half2*)(C + (size_t)rr * ldc + cb) =
                    __floats2half2_rn(acc[mt][nt][0], acc[mt][nt][1]);
                *(__half2*)(C + (size_t)(rr + 8) * ldc + cb) =
                    __floats2half2_rn(acc[mt][nt][2], acc[mt][nt][3]);
            } else {
                float* C = (float*)Cv;
                *(float2*)(C + (size_t)rr * ldc + cb) =
                    make_float2(acc[mt][nt][0], acc[mt][nt][1]);
                *(float2*)(C + (size_t)(rr + 8) * ldc + cb) =
                    make_float2(acc[mt][nt][2], acc[mt][nt][3]);
            }
        }
    }
}

// fused QKV projection: bx 0..15 -> Q, 16..23 -> K, 24..31 -> V (half outputs)
__global__ void __launch_bounds__(256, 2)
qkv_proj(const __half* __restrict__ xh,
         const __half* __restrict__ Wq, const __half* __restrict__ Wk,
         const __half* __restrict__ Wv,
         __half* __restrict__ Q, __half* __restrict__ K, __half* __restrict__ V)
{
    const int bx = blockIdx.x;
    const __half* Bp;  __half* Cp;  int ldc, n0;
    if (bx < 16)      { Bp = Wq; Cp = Q; ldc = D_;  n0 = bx * 128; }
    else if (bx < 24) { Bp = Wk; Cp = K; ldc = KVD; n0 = (bx - 16) * 128; }
    else              { Bp = Wv; Cp = V; ldc = KVD; n0 = (bx - 24) * 128; }
    gemm_f16_body<true>(xh, D_, Bp, D_, Cp, ldc, D_, blockIdx.y * 128, n0);
}

__global__ void __launch_bounds__(256, 2)
out_proj(const __half* __restrict__ Oh, const __half* __restrict__ Wo,
         float* __restrict__ out)
{
    gemm_f16_body<false>(Oh, D_, Wo, D_, out, D_, D_,
                         blockIdx.y * 128, blockIdx.x * 128);
}

// half transpose: Vh[b][t][n] -> Vth[b][n][t], 64x64 tiles
__global__ void __launch_bounds__(256)
transpose_vh(const __half* __restrict__ V, __half* __restrict__ Vt)
{
    __shared__ __half tile[64][66];
    const int b  = blockIdx.z;
    const int t0 = blockIdx.x << 6, n0 = blockIdx.y << 6;
    const int tx = threadIdx.x & 31, ty = threadIdx.x >> 5;
    const __half* src = V  + (size_t)b * T_ * KVD;
    __half*       dst = Vt + (size_t)b * KVD * T_;
    #pragma unroll
    for (int j = 0; j < 8; ++j) {
        int r = ty + (j << 3);
        __half2 h = *(const __half2*)(src + (size_t)(t0 + r) * KVD + n0 + 2 * tx);
        tile[2 * tx][r]     = __low2half(h);
        tile[2 * tx + 1][r] = __high2half(h);
    }
    __syncthreads();
    #pragma unroll
    for (int j = 0; j < 8; ++j) {
        int r = ty + (j << 3);
        __half2 h = __halves2half2(tile[r][2 * tx], tile[r][2 * tx + 1]);
        *(__half2*)(dst + (size_t)(n0 + r) * T_ + t0 + 2 * tx) = h;
    }
}

// ---------------------------------------------------------------------------
// fp16 flash attention: 128 threads (4 warps), 64 q-rows/CTA, KV tile 64,
// 2 CTAs per SM.  R9-proven strides/fragments.
// smem (halves): sK[2][64][136], sVt[2][128][72], sP[4][16][72] = 80896 B.
// ---------------------------------------------------------------------------
#define SKH 136
#define SVH 72
#define SPH 72
#define SKB (64 * SKH)     // 8704 halves
#define SVB (128 * SVH)    // 9216 halves
#define FLASH_SMEM ((2*SKB + 2*SVB + 4*16*SPH) * 2)   // 80896 B

__global__ void __launch_bounds__(128, 2)
flash_attn(const __half* __restrict__ Qg, const __half* __restrict__ Kg,
           const __half* __restrict__ Vtg, __half* __restrict__ Og)
{
    extern __shared__ __half hsm[];
    __half* sK  = hsm;
    __half* sVt = hsm + 2 * SKB;
    __half* sP  = hsm + 2 * SKB + 2 * SVB;

    const int tid  = threadIdx.x;
    const int lane = tid & 31;
    const int w    = tid >> 5;          // 0..3
    const int g    = lane >> 2;
    const int tg   = lane & 3;
    const int z    = blockIdx.y, b = z >> 4, hq = z & 15, kv = hq >> 1;
    const int m0   = blockIdx.x << 6;   // 64 q-rows per CTA
    const float inv_scale = 0.088388347648318447f;

    const size_t qbase  = (size_t)b * T_ * D_  + (size_t)hq * HD;
    const size_t kbase  = (size_t)b * T_ * KVD + (size_t)kv * HD;
    const size_t vtbase = ((size_t)b * KVD + (size_t)kv * HD) * T_;

    // ---- stage Q tile (64 x 128 halves) into sK region, stride SKH
    #pragma unroll
    for (int j = 0; j < 8; ++j) {
        int u = tid + (j << 7);
        int row = u >> 4, seg = (u & 15) << 3;
        cpa16(smem_u32(sK + row * SKH + seg),
              Qg + qbase + (size_t)(m0 + row) * D_ + seg);
    }
    asm volatile("cp.async.commit_group;" ::: "memory");
    asm volatile("cp.async.wait_group 0;" ::: "memory");
    __syncthreads();

    // Q fragments (scaled in fp32, rounded to half)
    uint32_t qf[8][4];
    {
        const __half* qr0 = sK + (w * 16 + g) * SKH;
        const __half* qr1 = qr0 + 8 * SKH;
        #pragma unroll
        for (int ks = 0; ks < 8; ++ks) {
            const int c = (ks << 4) + 2 * tg;
            #pragma unroll
            for (int h = 0; h < 2; ++h) {
                const int cc = c + h * 8;
                __half2 a0 = *(const __half2*)(qr0 + cc);
                __half2 a1 = *(const __half2*)(qr1 + cc);
                __half2 s0 = __floats2half2_rn(__low2float(a0) * inv_scale,
                                               __high2float(a0) * inv_scale);
                __half2 s1 = __floats2half2_rn(__low2float(a1) * inv_scale,
                                               __high2float(a1) * inv_scale);
                qf[ks][h * 2]     = *(uint32_t*)&s0;
                qf[ks][h * 2 + 1] = *(uint32_t*)&s1;
            }
        }
    }
    __syncthreads();

    float of[16][4];
    #pragma unroll
    for (int nt = 0; nt < 16; ++nt)
        #pragma unroll
        for (int r = 0; r < 4; ++r)
            of[nt][r] = 0.0f;
    float mprev0 = -1e30f, mprev1 = -1e30f, l0 = 0.0f, l1 = 0.0f;

    // stage kv iter 0: K 64x128, Vt 128x64
    #pragma unroll
    for (int j = 0; j < 8; ++j) {
        int u = tid + (j << 7);
        int kr = u >> 4, ks_ = (u & 15) << 3;
        cpa16(smem_u32(sK + kr * SKH + ks_), Kg + kbase + (size_t)kr * KVD + ks_);
        int vr = u >> 3, vs = (u & 7) << 3;
        cpa16(smem_u32(sVt + vr * SVH + vs), Vtg + vtbase + (size_t)vr * T_ + vs);
    }
    asm volatile("cp.async.commit_group;" ::: "memory");

    __half* Pw = sP + w * 16 * SPH;

    // ldmatrix lane offsets (bytes)
    const uint32_t sKsm = smem_u32(sK);
    const uint32_t sVsm = smem_u32(sVt);
    const uint32_t pWsm = smem_u32(Pw);
    const uint32_t kLane = (uint32_t)((((lane & 7) + ((lane >> 4) << 3)) * SKH
                                      + (((lane >> 3) & 1) << 3)) * 2);
    const uint32_t vLane = (uint32_t)((((lane & 7) + ((lane >> 4) << 3)) * SVH
                                      + (((lane >> 3) & 1) << 3)) * 2);
    const uint32_t pLane = (uint32_t)(((lane & 15) * SPH + ((lane >> 4) << 3)) * 2);

    for (int it = 0; it < 32; ++it) {
        const int buf = it & 1;
        if (it + 1 < 32) {
            const int nb = buf ^ 1;
            const int t0 = (it + 1) << 6;
            #pragma unroll
            for (int j = 0; j < 8; ++j) {
                int u = tid + (j << 7);
                int kr = u >> 4, ks_ = (u & 15) << 3;
                cpa16(smem_u32(sK + nb * SKB + kr * SKH + ks_),
                      Kg + kbase + (size_t)(t0 + kr) * KVD + ks_);
                int vr = u >> 3, vs = (u & 7) << 3;
                cpa16(smem_u32(sVt + nb * SVB + vr * SVH + vs),
                      Vtg + vtbase + (size_t)vr * T_ + t0 + vs);
            }
            asm volatile("cp.async.commit_group;" ::: "memory");
            asm volatile("cp.async.wait_group 1;" ::: "memory");
        } else {
            asm volatile("cp.async.wait_group 0;" ::: "memory");
        }
        __syncthreads();

        // S = Q @ K^T  (16 x 64 per warp, K via ldmatrix)
        float sf[8][4];
        #pragma unroll
        for (int nt = 0; nt < 8; ++nt)
            sf[nt][0] = sf[nt][1] = sf[nt][2] = sf[nt][3] = 0.0f;
        {
            const uint32_t kBase = sKsm + (uint32_t)(buf * SKB * 2) + kLane;
            #pragma unroll
            for (int ks = 0; ks < 8; ++ks) {
                const uint32_t kOff = (uint32_t)((ks << 4) * 2);
                #pragma unroll
                for (int p = 0; p < 4; ++p) {
                    uint32_t bf[4];
                    ldm_x4(bf, kBase + kOff + (uint32_t)(p * 16 * SKH * 2));
                    mma_f16(sf[2 * p],     qf[ks], &bf[0]);
                    mma_f16(sf[2 * p + 1], qf[ks], &bf[2]);
                }
            }
        }

        // online softmax
        float mx0 = mprev0, mx1 = mprev1;
        #pragma unroll
        for (int nt = 0; nt < 8; ++nt) {
            mx0 = fmaxf(mx0, fmaxf(sf[nt][0], sf[nt][1]));
            mx1 = fmaxf(mx1, fmaxf(sf[nt][2], sf[nt][3]));
        }
        mx0 = fmaxf(mx0, __shfl_xor_sync(0xffffffffu, mx0, 1));
        mx0 = fmaxf(mx0, __shfl_xor_sync(0xffffffffu, mx0, 2));
        mx1 = fmaxf(mx1, __shfl_xor_sync(0xffffffffu, mx1, 1));
        mx1 = fmaxf(mx1, __shfl_xor_sync(0xffffffffu, mx1, 2));

        const float sc0 = __expf(mprev0 - mx0);
        const float sc1 = __expf(mprev1 - mx1);
        mprev0 = mx0; mprev1 = mx1;

        float rs0 = 0.0f, rs1 = 0.0f;
        #pragma unroll
        for (int nt = 0; nt < 8; ++nt) {
            float p0 = __expf(sf[nt][0] - mx0);
            float p1 = __expf(sf[nt][1] - mx0);
            float p2 = __expf(sf[nt][2] - mx1);
            float p3 = __expf(sf[nt][3] - mx1);
            rs0 += p0 + p1;  rs1 += p2 + p3;
            *(__half2*)(Pw + g * SPH + nt * 8 + 2 * tg)       = __floats2half2_rn(p0, p1);
            *(__half2*)(Pw + (g + 8) * SPH + nt * 8 + 2 * tg) = __floats2half2_rn(p2, p3);
        }
        rs0 += __shfl_xor_sync(0xffffffffu, rs0, 1);
        rs0 += __shfl_xor_sync(0xffffffffu, rs0, 2);
        rs1 += __shfl_xor_sync(0xffffffffu, rs1, 1);
        rs1 += __shfl_xor_sync(0xffffffffu, rs1, 2);
        l0 = l0 * sc0 + rs0;
        l1 = l1 * sc1 + rs1;

        #pragma unroll
        for (int nt = 0; nt < 16; ++nt) {
            of[nt][0] *= sc0; of[nt][1] *= sc0;
            of[nt][2] *= sc1; of[nt][3] *= sc1;
        }
        __syncwarp();

        // O += P @ V  (16 x 128 per warp; P and Vt via ldmatrix)
        {
            const uint32_t pBase = pWsm + pLane;
            const uint32_t vBase = sVsm + (uint32_t)(buf * SVB * 2) + vLane;
            #pragma unroll
            for (int kc = 0; kc < 4; ++kc) {
                const uint32_t kOff = (uint32_t)((kc << 4) * 2);
                uint32_t aa[4];
                ldm_x4(aa, pBase + kOff);
                #pragma unroll
                for (int p = 0; p < 8; ++p) {
                    uint32_t bb[4];
                    ldm_x4(bb, vBase + kOff + (uint32_t)(p * 16 * SVH * 2));
                    mma_f16(of[2 * p],     aa, &bb[0]);
                    mma_f16(of[2 * p + 1], aa, &bb[2]);
                }
            }
        }
        __syncthreads();
    }

    // epilogue: O /= l, store half (input to fp16 out-proj)
    const float i0 = 1.0f / l0;
    const float i1 = 1.0f / l1;
    const int r0 = m0 + w * 16 + g;
    const size_t obase = (size_t)b * T_ * D_ + (size_t)hq * HD;
    #pragma unroll
    for (int nt = 0; nt < 16; ++nt) {
        const int c = nt * 8 + 2 * tg;
        *(__half2*)(Og + obase + (size_t)r0 * D_ + c) =
            __floats2half2_rn(of[nt][0] * i0, of[nt][1] * i0);
        *(__half2*)(Og + obase + (size_t)(r0 + 8) * D_ + c) =
            __floats2half2_rn(of[nt][2] * i1, of[nt][3] * i1);
    }
}

// fused conversion: all five fp32 tensors -> fp16 in one launch
#define N4_X  (BT  * D_ / 4)
#define N4_WQ (D_  * D_ / 4)
#define N4_WK (KVD * D_ / 4)
#define N4_WV (KVD * D_ / 4)
#define N4_WO (D_  * D_ / 4)
#define N4_TOT (N4_X + N4_WQ + N4_WK + N4_WV + N4_WO)

__global__ void __launch_bounds__(256)
to_half_all(const float4* __restrict__ x,  uint2* __restrict__ xh,
            const float4* __restrict__ wq, uint2* __restrict__ wqh,
            const float4* __restrict__ wk, uint2* __restrict__ wkh,
            const float4* __restrict__ wv, uint2* __restrict__ wvh,
            const float4* __restrict__ wo, uint2* __restrict__ woh)
{
    int i = blockIdx.x * blockDim.x + threadIdx.x;
    const int stride = gridDim.x * blockDim.x;
    for (; i < N4_TOT; i += stride) {
        const float4* src;  uint2* dst;  int off = i;
        if (off < N4_X)                        { src = x;  dst = xh; }
        else if ((off -= N4_X)  < N4_WQ)       { src = wq; dst = wqh; }
        else if ((off -= N4_WQ) < N4_WK)       { src = wk; dst = wkh; }
        else if ((off -= N4_WK) < N4_WV)       { src = wv; dst = wvh; }
        else { off -= N4_WV;                     src = wo; dst = woh; }
        float4 v = src[off];
        __half2 h0 = __floats2half2_rn(v.x, v.y);
        __half2 h1 = __floats2half2_rn(v.z, v.w);
        uint2 r;
        r.x = *(uint32_t*)&h0;
        r.y = *(uint32_t*)&h1;
        dst[off] = r;
    }
}

// ---------------- host ----------------
extern "C" void kernel_launch(void* const* d_in, const int* in_sizes, int n_in,
                              void* d_out, int out_size)
{
    (void)in_sizes; (void)n_in; (void)out_size;
    const float* x  = (const float*)d_in[0];
    const float* Wq = (const float*)d_in[1];
    const float* Wk = (const float*)d_in[2];
    const float* Wv = (const float*)d_in[3];
    const float* Wo = (const float*)d_in[4];
    float* out = (float*)d_out;

    __half *xh, *Wqh, *Wkh, *Wvh, *Woh, *Qh, *Kh, *Vh, *Vth, *Oh;
    cudaGetSymbolAddress((void**)&xh,  g_xh);
    cudaGetSymbolAddress((void**)&Wqh, g_Wqh);
    cudaGetSymbolAddress((void**)&Wkh, g_Wkh);
    cudaGetSymbolAddress((void**)&Wvh, g_Wvh);
    cudaGetSymbolAddress((void**)&Woh, g_Woh);
    cudaGetSymbolAddress((void**)&Qh,  g_Qh);
    cudaGetSymbolAddress((void**)&Kh,  g_Kh);
    cudaGetSymbolAddress((void**)&Vh,  g_Vh);
    cudaGetSymbolAddress((void**)&Vth, g_Vth);
    cudaGetSymbolAddress((void**)&Oh,  g_Oh);

    cudaFuncSetAttribute(qkv_proj, cudaFuncAttributeMaxDynamicSharedMemorySize,
                         GEMM_SMEM);
    cudaFuncSetAttribute(out_proj, cudaFuncAttributeMaxDynamicSharedMemorySize,
                         GEMM_SMEM);
    cudaFuncSetAttribute(flash_attn, cudaFuncAttributeMaxDynamicSharedMemorySize,
                         FLASH_SMEM);

    // fused conversion (one launch)
    to_half_all<<<2048, 256>>>((const float4*)x,  (uint2*)xh,
                               (const float4*)Wq, (uint2*)Wqh,
                               (const float4*)Wk, (uint2*)Wkh,
                               (const float4*)Wv, (uint2*)Wvh,
                               (const float4*)Wo, (uint2*)Woh);

    // fused Q/K/V projections (fp16 in, half out)
    qkv_proj<<<dim3(32, 32), 256, GEMM_SMEM>>>(xh, Wqh, Wkh, Wvh, Qh, Kh, Vh);
    transpose_vh<<<dim3(32, 16, 2), 256>>>(Vh, Vth);

    // fused fp16 attention: 64 q-rows/CTA, 2 CTAs per SM
    flash_attn<<<dim3(32, 32), 128, FLASH_SMEM>>>(Qh, Kh, Vth, Oh);

    // output projection (fp16 MMA; final fp32 output)
    out_proj<<<dim3(16, 32), 256, GEMM_SMEM>>>(Oh, Woh, out);
}